// round 1
// baseline (speedup 1.0000x reference)
#include <cuda_runtime.h>
#include <cstdint>
#include <cstddef>

// Problem constants
constexpr int B_ = 8;
constexpr int N_ = 2048;
constexpr int E_ = 512;
constexpr int H_ = 8;
constexpr int D_ = 64;
constexpr int M_ = B_ * N_;   // 16384 rows

// Scratch (device globals: allocation-free per harness rules)
__device__ float g_q[(size_t)B_ * H_ * N_ * D_];   // [b][h][n][d]
__device__ float g_k[(size_t)B_ * H_ * N_ * D_];
__device__ float g_v[(size_t)B_ * H_ * N_ * D_];
__device__ float g_att[(size_t)M_ * E_];           // [b*n][h*d] recombined heads

__device__ __forceinline__ float neg_inf() { return __int_as_float(0xff800000); }

// ---------------------------------------------------------------------------
// GEMM: Y = X @ W^T (+ bias).  X:[M,512] row-major, W:[512,512] row-major
// ([out,in], nn.Linear convention).
// MODE 0: X = Xin, output scattered to split-head scratch (tgt: 0=q,1=k,2=v)
// MODE 1: X = g_att, output row-major to Yext with bias
// Tiling: BM=BN=64, BK=16, 256 threads as 16x16, each thread 4x4.
// Smem tiles stored K-outer (transposed) with stride 68 so the inner loop is
// two conflict-free LDS.128 per 16 FMA.
// ---------------------------------------------------------------------------
template<int MODE>
__global__ __launch_bounds__(256)
void gemm_xwt(const float* __restrict__ Xin, const float* __restrict__ W,
              const float* __restrict__ bias, float* __restrict__ Yext, int tgt)
{
    __shared__ float As[16 * 68];
    __shared__ float Bs[16 * 68];
    const int tid = threadIdx.x;
    const int tx = tid & 15, ty = tid >> 4;
    const int m0 = blockIdx.y * 64, n0 = blockIdx.x * 64;
    const int lrow = tid >> 2;      // 0..63
    const int lc4  = tid & 3;       // 0..3  (covers 16 k-values as 4 float4s? no: 4 groups of 4)
    const float* X = (MODE == 1) ? g_att : Xin;

    float acc[4][4] = {};

    for (int kt = 0; kt < E_; kt += 16) {
        // 64 rows x 16 k each for X and W: one float4 per thread per tile
        float4 xa = *reinterpret_cast<const float4*>(X + (size_t)(m0 + lrow) * E_ + kt + lc4 * 4);
        float4 wb = *reinterpret_cast<const float4*>(W + (size_t)(n0 + lrow) * E_ + kt + lc4 * 4);
        As[(lc4 * 4 + 0) * 68 + lrow] = xa.x;
        As[(lc4 * 4 + 1) * 68 + lrow] = xa.y;
        As[(lc4 * 4 + 2) * 68 + lrow] = xa.z;
        As[(lc4 * 4 + 3) * 68 + lrow] = xa.w;
        Bs[(lc4 * 4 + 0) * 68 + lrow] = wb.x;
        Bs[(lc4 * 4 + 1) * 68 + lrow] = wb.y;
        Bs[(lc4 * 4 + 2) * 68 + lrow] = wb.z;
        Bs[(lc4 * 4 + 3) * 68 + lrow] = wb.w;
        __syncthreads();
        #pragma unroll
        for (int kk = 0; kk < 16; kk++) {
            float a_r[4], b_r[4];
            *reinterpret_cast<float4*>(a_r) = *reinterpret_cast<const float4*>(&As[kk * 68 + ty * 4]);
            *reinterpret_cast<float4*>(b_r) = *reinterpret_cast<const float4*>(&Bs[kk * 68 + tx * 4]);
            #pragma unroll
            for (int i = 0; i < 4; i++)
                #pragma unroll
                for (int j = 0; j < 4; j++)
                    acc[i][j] += a_r[i] * b_r[j];
        }
        __syncthreads();
    }

    if (MODE == 0) {
        float* Y = (tgt == 0) ? g_q : (tgt == 1) ? g_k : g_v;
        const int h = n0 >> 6;          // BN=64 == head dim, so one head per block col
        const int dd0 = tx * 4;         // n0 % 64 == 0
        #pragma unroll
        for (int i = 0; i < 4; i++) {
            int m = m0 + ty * 4 + i;
            int b = m >> 11;            // / N_
            int n = m & (N_ - 1);
            float4 w4 = make_float4(acc[i][0], acc[i][1], acc[i][2], acc[i][3]);
            *reinterpret_cast<float4*>(
                &Y[((size_t)((b * H_ + h) * N_ + n)) * D_ + dd0]) = w4;
        }
    } else {
        const int o0 = n0 + tx * 4;
        float4 bb = *reinterpret_cast<const float4*>(bias + o0);
        #pragma unroll
        for (int i = 0; i < 4; i++) {
            int m = m0 + ty * 4 + i;
            float4 w4 = make_float4(acc[i][0] + bb.x, acc[i][1] + bb.y,
                                    acc[i][2] + bb.z, acc[i][3] + bb.w);
            *reinterpret_cast<float4*>(&Yext[(size_t)m * E_ + o0]) = w4;
        }
    }
}

// ---------------------------------------------------------------------------
// Flash attention, fp32. One block = (b, h, 64 q rows). Loops over 32 kv
// tiles of 64. Online softmax with running (m, l); O kept in registers
// (16x16 threads x 4x4). Mask applied generically (mask==0 -> -inf).
// Grid ordered so the 8 heads of a (b, q-tile) are adjacent -> mask tile hits L2.
// ---------------------------------------------------------------------------
__global__ __launch_bounds__(256)
void attn_kernel(const int* __restrict__ mask, const float* __restrict__ taup)
{
    extern __shared__ float sm[];
    float* Qs   = sm;                 // [64 k][68] transposed Q tile
    float* Ks   = Qs + 64 * 68;       // [64 k][68] transposed K tile
    float* Vs   = Ks + 64 * 68;       // [64 j][68] V tile (row-major)
    float* Ss   = Vs + 64 * 68;       // [64 r][68] scores / probabilities
    float* m_sh = Ss + 64 * 68;       // [64] running max
    float* l_sh = m_sh + 64;          // [64] running sum
    float* c_sh = l_sh + 64;          // [64] per-tile rescale factor

    const int h = blockIdx.x, qt = blockIdx.y, b = blockIdx.z;
    const int tid = threadIdx.x;
    const int tx = tid & 15, ty = tid >> 4;
    const int q0 = qt * 64;
    const float inv_tau = 1.0f / taup[0];

    const size_t bh = (size_t)(b * H_ + h) * N_ * D_;
    const float* qbase = g_q + bh;
    const float* kbase = g_k + bh;
    const float* vbase = g_v + bh;
    const int*   mbase = mask + (size_t)b * N_ * N_;

    // Load Q tile, transposed into Qs[kk][row]
    for (int t = tid; t < 1024; t += 256) {
        int r = t >> 4, c4 = t & 15;
        float4 v = *reinterpret_cast<const float4*>(qbase + (size_t)(q0 + r) * D_ + c4 * 4);
        Qs[(c4 * 4 + 0) * 68 + r] = v.x;
        Qs[(c4 * 4 + 1) * 68 + r] = v.y;
        Qs[(c4 * 4 + 2) * 68 + r] = v.z;
        Qs[(c4 * 4 + 3) * 68 + r] = v.w;
    }
    if (tid < 64) { m_sh[tid] = neg_inf(); l_sh[tid] = 0.0f; }

    float o[4][4] = {};

    for (int kv0 = 0; kv0 < N_; kv0 += 64) {
        __syncthreads();  // prior gemm2 done; safe to overwrite Ks/Vs
        // Load K (transposed) and V (row-major) tiles
        for (int t = tid; t < 1024; t += 256) {
            int j = t >> 4, c4 = t & 15;
            float4 kv = *reinterpret_cast<const float4*>(kbase + (size_t)(kv0 + j) * D_ + c4 * 4);
            Ks[(c4 * 4 + 0) * 68 + j] = kv.x;
            Ks[(c4 * 4 + 1) * 68 + j] = kv.y;
            Ks[(c4 * 4 + 2) * 68 + j] = kv.z;
            Ks[(c4 * 4 + 3) * 68 + j] = kv.w;
            float4 vv = *reinterpret_cast<const float4*>(vbase + (size_t)(kv0 + j) * D_ + c4 * 4);
            *reinterpret_cast<float4*>(&Vs[j * 68 + c4 * 4]) = vv;
        }
        __syncthreads();

        // S = Q @ K^T  (thread 4x4 tile)
        float s[4][4] = {};
        #pragma unroll 16
        for (int kk = 0; kk < 64; kk++) {
            float a_r[4], b_r[4];
            *reinterpret_cast<float4*>(a_r) = *reinterpret_cast<const float4*>(&Qs[kk * 68 + ty * 4]);
            *reinterpret_cast<float4*>(b_r) = *reinterpret_cast<const float4*>(&Ks[kk * 68 + tx * 4]);
            #pragma unroll
            for (int i = 0; i < 4; i++)
                #pragma unroll
                for (int j = 0; j < 4; j++)
                    s[i][j] += a_r[i] * b_r[j];
        }

        // Apply mask + 1/tau, write to Ss
        #pragma unroll
        for (int i = 0; i < 4; i++) {
            int4 mv = *reinterpret_cast<const int4*>(
                mbase + (size_t)(q0 + ty * 4 + i) * N_ + kv0 + tx * 4);
            float* row = &Ss[(ty * 4 + i) * 68 + tx * 4];
            row[0] = (mv.x != 0) ? s[i][0] * inv_tau : neg_inf();
            row[1] = (mv.y != 0) ? s[i][1] * inv_tau : neg_inf();
            row[2] = (mv.z != 0) ? s[i][2] * inv_tau : neg_inf();
            row[3] = (mv.w != 0) ? s[i][3] * inv_tau : neg_inf();
        }
        __syncthreads();

        // Online softmax: 4 threads per row, 16 cols each
        {
            int r = tid >> 2, c4 = tid & 3;
            float mprev = m_sh[r];
            float mx = neg_inf();
            #pragma unroll
            for (int i = 0; i < 16; i++)
                mx = fmaxf(mx, Ss[r * 68 + c4 * 16 + i]);
            mx = fmaxf(mx, __shfl_xor_sync(0xffffffffu, mx, 1));
            mx = fmaxf(mx, __shfl_xor_sync(0xffffffffu, mx, 2));
            float mnew = fmaxf(mprev, mx);
            float scale, sum = 0.0f;
            if (mnew == neg_inf()) {   // fully masked so far
                scale = 1.0f;
                #pragma unroll
                for (int i = 0; i < 16; i++) Ss[r * 68 + c4 * 16 + i] = 0.0f;
            } else {
                scale = __expf(mprev - mnew);   // exp(-inf)=0 when mprev=-inf
                #pragma unroll
                for (int i = 0; i < 16; i++) {
                    float p = __expf(Ss[r * 68 + c4 * 16 + i] - mnew);
                    Ss[r * 68 + c4 * 16 + i] = p;
                    sum += p;
                }
            }
            sum += __shfl_xor_sync(0xffffffffu, sum, 1);
            sum += __shfl_xor_sync(0xffffffffu, sum, 2);
            if (c4 == 0) {
                l_sh[r] = l_sh[r] * scale + sum;
                m_sh[r] = mnew;
                c_sh[r] = scale;
            }
        }
        __syncthreads();

        // Rescale O, then O += P @ V
        #pragma unroll
        for (int i = 0; i < 4; i++) {
            float sc = c_sh[ty * 4 + i];
            #pragma unroll
            for (int j = 0; j < 4; j++) o[i][j] *= sc;
        }
        #pragma unroll 16
        for (int kk = 0; kk < 64; kk++) {
            float v_r[4];
            *reinterpret_cast<float4*>(v_r) = *reinterpret_cast<const float4*>(&Vs[kk * 68 + tx * 4]);
            float p_r[4];
            #pragma unroll
            for (int u = 0; u < 4; u++) p_r[u] = Ss[(ty * 4 + u) * 68 + kk];
            #pragma unroll
            for (int u = 0; u < 4; u++)
                #pragma unroll
                for (int j = 0; j < 4; j++)
                    o[u][j] += p_r[u] * v_r[j];
        }
    }
    __syncthreads();

    // Epilogue: divide by l, recombine heads into [b*n][h*64+d]
    #pragma unroll
    for (int i = 0; i < 4; i++) {
        int r = ty * 4 + i;
        float inv = 1.0f / l_sh[r];
        float4 w4 = make_float4(o[i][0] * inv, o[i][1] * inv, o[i][2] * inv, o[i][3] * inv);
        *reinterpret_cast<float4*>(
            &g_att[(size_t)(b * N_ + q0 + r) * E_ + h * 64 + tx * 4]) = w4;
    }
}

// ---------------------------------------------------------------------------
extern "C" void kernel_launch(void* const* d_in, const int* in_sizes, int n_in,
                              void* d_out, int out_size)
{
    const float* Q    = (const float*)d_in[0];
    const float* K    = (const float*)d_in[1];
    const float* V    = (const float*)d_in[2];
    const int*   mask = (const int*)  d_in[3];
    const float* Wq   = (const float*)d_in[4];
    const float* Wk   = (const float*)d_in[5];
    const float* Wv   = (const float*)d_in[6];
    const float* Wo   = (const float*)d_in[7];
    const float* bo   = (const float*)d_in[8];
    const float* tau  = (const float*)d_in[9];
    float* out = (float*)d_out;

    dim3 gg(E_ / 64, M_ / 64);   // 8 x 256 blocks

    gemm_xwt<0><<<gg, 256>>>(Q, Wq, nullptr, nullptr, 0);
    gemm_xwt<0><<<gg, 256>>>(K, Wk, nullptr, nullptr, 1);
    gemm_xwt<0><<<gg, 256>>>(V, Wv, nullptr, nullptr, 2);

    const int smem_bytes = (4 * 64 * 68 + 3 * 64) * (int)sizeof(float);  // 70400
    cudaFuncSetAttribute(attn_kernel, cudaFuncAttributeMaxDynamicSharedMemorySize, smem_bytes);
    // grid.x = heads (fastest) so the 8 heads sharing a mask tile are adjacent -> L2 reuse
    attn_kernel<<<dim3(H_, N_ / 64, B_), 256, smem_bytes>>>(mask, tau);

    gemm_xwt<1><<<gg, 256>>>(nullptr, Wo, bo, out, 0);
}

// round 3
// speedup vs baseline: 1.3568x; 1.3568x over previous
#include <cuda_runtime.h>
#include <cstdint>
#include <cstddef>

// Problem constants
constexpr int B_ = 8;
constexpr int N_ = 2048;
constexpr int E_ = 512;
constexpr int H_ = 8;
constexpr int D_ = 64;
constexpr int M_ = B_ * N_;   // 16384 rows

// Scratch (device globals: allocation-free per harness rules)
__device__ float g_q[(size_t)B_ * H_ * N_ * D_];   // [b][h][n][d]
__device__ float g_k[(size_t)B_ * H_ * N_ * D_];
__device__ float g_v[(size_t)B_ * H_ * N_ * D_];
__device__ float g_att[(size_t)M_ * E_];           // [b*n][h*d] recombined heads

__device__ __forceinline__ float neg_inf() { return __int_as_float(0xff800000); }

// round-to-nearest tf32, result kept as float bit pattern (low 13 mantissa bits zero)
__device__ __forceinline__ float f2tf(float x) {
    uint32_t r;
    asm("cvt.rna.tf32.f32 %0, %1;" : "=r"(r) : "f"(x));
    return __uint_as_float(r);
}

// m16n8k8 tf32 mma: c += a * b  (a: 4 regs, b: 2 regs, c: 4 f32)
__device__ __forceinline__ void mma8(float* c, const uint32_t* a, const uint32_t* b) {
    asm volatile(
        "mma.sync.aligned.m16n8k8.row.col.f32.tf32.tf32.f32 "
        "{%0,%1,%2,%3}, {%4,%5,%6,%7}, {%8,%9}, {%0,%1,%2,%3};\n"
        : "+f"(c[0]), "+f"(c[1]), "+f"(c[2]), "+f"(c[3])
        : "r"(a[0]), "r"(a[1]), "r"(a[2]), "r"(a[3]), "r"(b[0]), "r"(b[1]));
}

// ---------------------------------------------------------------------------
// GEMM: Y = X @ W^T (+bias) with 3xTF32 (hi/lo split, 3 mma passes) for
// near-fp32 accuracy. X:[M,512], W:[512,512] row-major ([out,in]).
// Block 128x64, BK=32, 256 thr = 8 warps as 4(m) x 2(n), warp tile 32x32.
// Smem tiles padded to stride 36 -> fragment LDS.32 are bank-conflict-free
// (bank = (g*4 + t) % 32, all lanes distinct).
// MODE 0: scatter to split-head scratch (tgt 0=q,1=k,2=v); MODE 1: g_att -> Yext + bias.
// ---------------------------------------------------------------------------
template<int MODE>
__global__ __launch_bounds__(256)
void gemm_tf32x3(const float* __restrict__ Xin, const float* __restrict__ W,
                 const float* __restrict__ bias, float* __restrict__ Yext, int tgt)
{
    extern __shared__ float sm[];
    float* Xh = sm;                    // [128][36]
    float* Xl = Xh + 128 * 36;
    float* Wh = Xl + 128 * 36;         // [64][36]
    float* Wl = Wh + 64 * 36;

    const int tid = threadIdx.x;
    const int warp = tid >> 5, lane = tid & 31;
    const int g = lane >> 2, tg = lane & 3;
    const int wm = warp >> 1, wn = warp & 1;
    const int m0 = blockIdx.y * 128, n0 = blockIdx.x * 64;
    const float* X = (MODE == 1) ? g_att : Xin;

    float acc[2][4][4] = {};   // [mt][nt][c]

    const int xr = tid >> 1, xk0 = (tid & 1) * 16;
    const int wr = tid >> 2, wk0 = (tid & 3) * 8;

    for (int kt = 0; kt < E_; kt += 32) {
        __syncthreads();
        // X tile: 128x32, 16 elems/thread; split hi/lo on store
        #pragma unroll
        for (int i = 0; i < 4; i++) {
            float4 v = *reinterpret_cast<const float4*>(X + (size_t)(m0 + xr) * E_ + kt + xk0 + i * 4);
            float h0 = f2tf(v.x), h1 = f2tf(v.y), h2 = f2tf(v.z), h3 = f2tf(v.w);
            *reinterpret_cast<float4*>(&Xh[xr * 36 + xk0 + i * 4]) = make_float4(h0, h1, h2, h3);
            *reinterpret_cast<float4*>(&Xl[xr * 36 + xk0 + i * 4]) =
                make_float4(f2tf(v.x - h0), f2tf(v.y - h1), f2tf(v.z - h2), f2tf(v.w - h3));
        }
        // W tile: 64x32, 8 elems/thread
        #pragma unroll
        for (int i = 0; i < 2; i++) {
            float4 v = *reinterpret_cast<const float4*>(W + (size_t)(n0 + wr) * E_ + kt + wk0 + i * 4);
            float h0 = f2tf(v.x), h1 = f2tf(v.y), h2 = f2tf(v.z), h3 = f2tf(v.w);
            *reinterpret_cast<float4*>(&Wh[wr * 36 + wk0 + i * 4]) = make_float4(h0, h1, h2, h3);
            *reinterpret_cast<float4*>(&Wl[wr * 36 + wk0 + i * 4]) =
                make_float4(f2tf(v.x - h0), f2tf(v.y - h1), f2tf(v.z - h2), f2tf(v.w - h3));
        }
        __syncthreads();

        #pragma unroll
        for (int ks = 0; ks < 4; ks++) {
            const int k0 = ks * 8;
            uint32_t Ah[2][4], Al[2][4], Bh[4][2], Bl[4][2];
            #pragma unroll
            for (int mt = 0; mt < 2; mt++) {
                const int rb = (wm * 32 + mt * 16) * 36 + k0;
                Ah[mt][0] = __float_as_uint(Xh[rb + g * 36 + tg]);
                Ah[mt][1] = __float_as_uint(Xh[rb + (g + 8) * 36 + tg]);
                Ah[mt][2] = __float_as_uint(Xh[rb + g * 36 + tg + 4]);
                Ah[mt][3] = __float_as_uint(Xh[rb + (g + 8) * 36 + tg + 4]);
                Al[mt][0] = __float_as_uint(Xl[rb + g * 36 + tg]);
                Al[mt][1] = __float_as_uint(Xl[rb + (g + 8) * 36 + tg]);
                Al[mt][2] = __float_as_uint(Xl[rb + g * 36 + tg + 4]);
                Al[mt][3] = __float_as_uint(Xl[rb + (g + 8) * 36 + tg + 4]);
            }
            #pragma unroll
            for (int nt = 0; nt < 4; nt++) {
                const int rb = (wn * 32 + nt * 8 + g) * 36 + k0;
                Bh[nt][0] = __float_as_uint(Wh[rb + tg]);
                Bh[nt][1] = __float_as_uint(Wh[rb + tg + 4]);
                Bl[nt][0] = __float_as_uint(Wl[rb + tg]);
                Bl[nt][1] = __float_as_uint(Wl[rb + tg + 4]);
            }
            #pragma unroll
            for (int mt = 0; mt < 2; mt++)
                #pragma unroll
                for (int nt = 0; nt < 4; nt++) {
                    mma8(acc[mt][nt], Ah[mt], Bh[nt]);   // hi*hi
                    mma8(acc[mt][nt], Ah[mt], Bl[nt]);   // hi*lo
                    mma8(acc[mt][nt], Al[mt], Bh[nt]);   // lo*hi
                }
        }
    }

    // Epilogue
    if (MODE == 0) {
        float* Y = (tgt == 0) ? g_q : (tgt == 1) ? g_k : g_v;
        const int h = blockIdx.x;              // BN=64 == head dim
        #pragma unroll
        for (int mt = 0; mt < 2; mt++) {
            #pragma unroll
            for (int nt = 0; nt < 4; nt++) {
                const int dd = wn * 32 + nt * 8 + 2 * tg;
                int m = m0 + wm * 32 + mt * 16 + g;
                int b = m >> 11, n = m & (N_ - 1);
                *reinterpret_cast<float2*>(&Y[((size_t)((b * H_ + h) * N_ + n)) * D_ + dd]) =
                    make_float2(acc[mt][nt][0], acc[mt][nt][1]);
                m += 8; b = m >> 11; n = m & (N_ - 1);
                *reinterpret_cast<float2*>(&Y[((size_t)((b * H_ + h) * N_ + n)) * D_ + dd]) =
                    make_float2(acc[mt][nt][2], acc[mt][nt][3]);
            }
        }
    } else {
        #pragma unroll
        for (int mt = 0; mt < 2; mt++) {
            #pragma unroll
            for (int nt = 0; nt < 4; nt++) {
                const int o = n0 + wn * 32 + nt * 8 + 2 * tg;
                float2 bb = *reinterpret_cast<const float2*>(bias + o);
                const int m = m0 + wm * 32 + mt * 16 + g;
                *reinterpret_cast<float2*>(&Yext[(size_t)m * E_ + o]) =
                    make_float2(acc[mt][nt][0] + bb.x, acc[mt][nt][1] + bb.y);
                *reinterpret_cast<float2*>(&Yext[(size_t)(m + 8) * E_ + o]) =
                    make_float2(acc[mt][nt][2] + bb.x, acc[mt][nt][3] + bb.y);
            }
        }
    }
}

// ---------------------------------------------------------------------------
// Flash attention with tf32 mma.sync. Block = (h, q-tile of 64, b), 4 warps,
// each warp owns 16 q rows. KV tiles of 64. S/P live in c-fragments; softmax
// stats per-thread (2 rows) reduced over the 4 lanes sharing a row. P goes
// through a per-warp smem tile to convert c-frag -> a-frag layout for P@V.
// Smem tiles stride 68 -> all fragment LDS are bank-conflict-free.
// ---------------------------------------------------------------------------
__global__ __launch_bounds__(128)
void attn_tc(const int* __restrict__ mask, const float* __restrict__ taup)
{
    extern __shared__ float sm[];
    float* Qs = sm;                 // [64][68] tf32
    float* Ks = Qs + 64 * 68;       // [64 kv][68 d] tf32
    float* Vs = Ks + 64 * 68;       // [64 kv][68 d] tf32
    float* Ps = Vs + 64 * 68;       // [64 q][68 kv] tf32 (per-warp 16-row slices)

    const int h = blockIdx.x, qt = blockIdx.y, b = blockIdx.z;
    const int tid = threadIdx.x;
    const int warp = tid >> 5, lane = tid & 31;
    const int g = lane >> 2, tg = lane & 3;
    const int q0 = qt * 64;
    const float inv_tau = 1.0f / __ldg(taup);

    const size_t bh = (size_t)(b * H_ + h) * N_ * D_;
    const float* qbase = g_q + bh;
    const float* kbase = g_k + bh;
    const float* vbase = g_v + bh;
    const int* mbase = mask + (size_t)b * N_ * N_;

    // Load Q tile (tf32-rounded): 64x64, 32 elems/thread
    {
        const int r = tid >> 1, c0 = (tid & 1) * 32;
        #pragma unroll
        for (int i = 0; i < 8; i++) {
            float4 v = *reinterpret_cast<const float4*>(qbase + (size_t)(q0 + r) * D_ + c0 + i * 4);
            *reinterpret_cast<float4*>(&Qs[r * 68 + c0 + i * 4]) =
                make_float4(f2tf(v.x), f2tf(v.y), f2tf(v.z), f2tf(v.w));
        }
    }

    float o[8][4] = {};                           // O c-frags: [d-tile][c]
    float mr0 = neg_inf(), mr1 = neg_inf();       // running max (rows g, g+8)
    float lr0 = 0.0f, lr1 = 0.0f;                 // running sum

    const int qrow = q0 + warp * 16 + g;          // global q row for c0/c1

    for (int kv0 = 0; kv0 < N_; kv0 += 64) {
        __syncthreads();   // all warps done with previous K/V
        // Load K,V tiles (tf32): each 64x64, 32 elems/thread each
        {
            const int r = tid >> 1, c0 = (tid & 1) * 32;
            #pragma unroll
            for (int i = 0; i < 8; i++) {
                float4 kv = *reinterpret_cast<const float4*>(kbase + (size_t)(kv0 + r) * D_ + c0 + i * 4);
                *reinterpret_cast<float4*>(&Ks[r * 68 + c0 + i * 4]) =
                    make_float4(f2tf(kv.x), f2tf(kv.y), f2tf(kv.z), f2tf(kv.w));
                float4 vv = *reinterpret_cast<const float4*>(vbase + (size_t)(kv0 + r) * D_ + c0 + i * 4);
                *reinterpret_cast<float4*>(&Vs[r * 68 + c0 + i * 4]) =
                    make_float4(f2tf(vv.x), f2tf(vv.y), f2tf(vv.z), f2tf(vv.w));
            }
        }
        __syncthreads();

        // S = Q @ K^T : warp computes 16 x 64
        float s[8][4] = {};
        #pragma unroll
        for (int kp = 0; kp < 8; kp++) {
            uint32_t a[4];
            const int qb = (warp * 16) * 68 + kp * 8;
            a[0] = __float_as_uint(Qs[qb + g * 68 + tg]);
            a[1] = __float_as_uint(Qs[qb + (g + 8) * 68 + tg]);
            a[2] = __float_as_uint(Qs[qb + g * 68 + tg + 4]);
            a[3] = __float_as_uint(Qs[qb + (g + 8) * 68 + tg + 4]);
            #pragma unroll
            for (int nt = 0; nt < 8; nt++) {
                uint32_t bfr[2];
                const int kb = (nt * 8 + g) * 68 + kp * 8 + tg;
                bfr[0] = __float_as_uint(Ks[kb]);
                bfr[1] = __float_as_uint(Ks[kb + 4]);
                mma8(s[nt], a, bfr);
            }
        }

        // mask + 1/tau
        #pragma unroll
        for (int nt = 0; nt < 8; nt++) {
            const int col = kv0 + nt * 8 + 2 * tg;
            int2 mA = *reinterpret_cast<const int2*>(mbase + (size_t)qrow * N_ + col);
            int2 mB = *reinterpret_cast<const int2*>(mbase + (size_t)(qrow + 8) * N_ + col);
            s[nt][0] = mA.x ? s[nt][0] * inv_tau : neg_inf();
            s[nt][1] = mA.y ? s[nt][1] * inv_tau : neg_inf();
            s[nt][2] = mB.x ? s[nt][2] * inv_tau : neg_inf();
            s[nt][3] = mB.y ? s[nt][3] * inv_tau : neg_inf();
        }

        // online softmax (rows g and g+8)
        float mx0 = neg_inf(), mx1 = neg_inf();
        #pragma unroll
        for (int nt = 0; nt < 8; nt++) {
            mx0 = fmaxf(mx0, fmaxf(s[nt][0], s[nt][1]));
            mx1 = fmaxf(mx1, fmaxf(s[nt][2], s[nt][3]));
        }
        mx0 = fmaxf(mx0, __shfl_xor_sync(0xffffffffu, mx0, 1));
        mx0 = fmaxf(mx0, __shfl_xor_sync(0xffffffffu, mx0, 2));
        mx1 = fmaxf(mx1, __shfl_xor_sync(0xffffffffu, mx1, 1));
        mx1 = fmaxf(mx1, __shfl_xor_sync(0xffffffffu, mx1, 2));
        const float mn0 = fmaxf(mr0, mx0), mn1 = fmaxf(mr1, mx1);
        // fmaxf(x, -80) absorbs -inf/NaN edge cases (fully masked rows) into exp->~0
        const float sc0 = __expf(fmaxf(mr0 - mn0, -80.0f));
        const float sc1 = __expf(fmaxf(mr1 - mn1, -80.0f));
        float sum0 = 0.0f, sum1 = 0.0f;
        #pragma unroll
        for (int nt = 0; nt < 8; nt++) {
            float p0 = __expf(fmaxf(s[nt][0] - mn0, -80.0f));
            float p1 = __expf(fmaxf(s[nt][1] - mn0, -80.0f));
            float p2 = __expf(fmaxf(s[nt][2] - mn1, -80.0f));
            float p3 = __expf(fmaxf(s[nt][3] - mn1, -80.0f));
            s[nt][0] = p0; s[nt][1] = p1; s[nt][2] = p2; s[nt][3] = p3;
            sum0 += p0 + p1; sum1 += p2 + p3;
        }
        sum0 += __shfl_xor_sync(0xffffffffu, sum0, 1);
        sum0 += __shfl_xor_sync(0xffffffffu, sum0, 2);
        sum1 += __shfl_xor_sync(0xffffffffu, sum1, 1);
        sum1 += __shfl_xor_sync(0xffffffffu, sum1, 2);
        lr0 = lr0 * sc0 + sum0; lr1 = lr1 * sc1 + sum1;
        mr0 = mn0; mr1 = mn1;

        // rescale O
        #pragma unroll
        for (int dt = 0; dt < 8; dt++) {
            o[dt][0] *= sc0; o[dt][1] *= sc0;
            o[dt][2] *= sc1; o[dt][3] *= sc1;
        }

        // P -> smem (tf32), c-frag layout -> a-frag layout fix-up
        #pragma unroll
        for (int nt = 0; nt < 8; nt++) {
            const int pb = (warp * 16 + g) * 68 + nt * 8 + 2 * tg;
            *reinterpret_cast<float2*>(&Ps[pb]) = make_float2(f2tf(s[nt][0]), f2tf(s[nt][1]));
            *reinterpret_cast<float2*>(&Ps[pb + 8 * 68]) = make_float2(f2tf(s[nt][2]), f2tf(s[nt][3]));
        }
        __syncwarp();

        // O += P @ V
        #pragma unroll
        for (int kp = 0; kp < 8; kp++) {
            uint32_t a[4];
            const int pb = (warp * 16) * 68 + kp * 8;
            a[0] = __float_as_uint(Ps[pb + g * 68 + tg]);
            a[1] = __float_as_uint(Ps[pb + (g + 8) * 68 + tg]);
            a[2] = __float_as_uint(Ps[pb + g * 68 + tg + 4]);
            a[3] = __float_as_uint(Ps[pb + (g + 8) * 68 + tg + 4]);
            #pragma unroll
            for (int dt = 0; dt < 8; dt++) {
                uint32_t bfr[2];
                const int vb = (kp * 8 + tg) * 68 + dt * 8 + g;
                bfr[0] = __float_as_uint(Vs[vb]);
                bfr[1] = __float_as_uint(Vs[vb + 4 * 68]);
                mma8(o[dt], a, bfr);
            }
        }
        __syncwarp();  // PV reads done before next iteration overwrites Ps
    }

    // Epilogue: normalize and recombine heads
    const float il0 = 1.0f / lr0, il1 = 1.0f / lr1;
    #pragma unroll
    for (int dt = 0; dt < 8; dt++) {
        const int dd = h * 64 + dt * 8 + 2 * tg;
        *reinterpret_cast<float2*>(&g_att[(size_t)(b * N_ + qrow) * E_ + dd]) =
            make_float2(o[dt][0] * il0, o[dt][1] * il0);
        *reinterpret_cast<float2*>(&g_att[(size_t)(b * N_ + qrow + 8) * E_ + dd]) =
            make_float2(o[dt][2] * il1, o[dt][3] * il1);
    }
}

// ---------------------------------------------------------------------------
extern "C" void kernel_launch(void* const* d_in, const int* in_sizes, int n_in,
                              void* d_out, int out_size)
{
    const float* Q    = (const float*)d_in[0];
    const float* K    = (const float*)d_in[1];
    const float* V    = (const float*)d_in[2];
    const int*   mask = (const int*)  d_in[3];
    const float* Wq   = (const float*)d_in[4];
    const float* Wk   = (const float*)d_in[5];
    const float* Wv   = (const float*)d_in[6];
    const float* Wo   = (const float*)d_in[7];
    const float* bo   = (const float*)d_in[8];
    const float* tau  = (const float*)d_in[9];
    float* out = (float*)d_out;

    const int gemm_smem = (128 * 36 * 2 + 64 * 36 * 2) * (int)sizeof(float);  // 55296
    const int attn_smem = 4 * 64 * 68 * (int)sizeof(float);                   // 69632

    cudaFuncSetAttribute(gemm_tf32x3<0>, cudaFuncAttributeMaxDynamicSharedMemorySize, gemm_smem);
    cudaFuncSetAttribute(gemm_tf32x3<1>, cudaFuncAttributeMaxDynamicSharedMemorySize, gemm_smem);
    cudaFuncSetAttribute(attn_tc, cudaFuncAttributeMaxDynamicSharedMemorySize, attn_smem);

    dim3 gg(E_ / 64, M_ / 128);   // 8 x 128 blocks

    gemm_tf32x3<0><<<gg, 256, gemm_smem>>>(Q, Wq, nullptr, nullptr, 0);
    gemm_tf32x3<0><<<gg, 256, gemm_smem>>>(K, Wk, nullptr, nullptr, 1);
    gemm_tf32x3<0><<<gg, 256, gemm_smem>>>(V, Wv, nullptr, nullptr, 2);

    // grid.x = heads (fastest) so the 8 heads sharing a mask tile are adjacent -> L2 reuse
    attn_tc<<<dim3(H_, N_ / 64, B_), 128, attn_smem>>>(mask, tau);

    gemm_tf32x3<1><<<gg, 256, gemm_smem>>>(nullptr, Wo, bo, out, 0);
}

// round 4
// speedup vs baseline: 1.5334x; 1.1302x over previous
#include <cuda_runtime.h>
#include <cstdint>
#include <cstddef>

// Problem constants
constexpr int B_ = 8;
constexpr int N_ = 2048;
constexpr int E_ = 512;
constexpr int H_ = 8;
constexpr int D_ = 64;
constexpr int M_ = B_ * N_;   // 16384 rows
constexpr int NT_ = N_ / 64;  // 32 kv/q tiles

// Scratch (device globals: allocation-free per harness rules)
__device__ float g_q[(size_t)B_ * H_ * N_ * D_];   // [b][h][n][d]
__device__ float g_k[(size_t)B_ * H_ * N_ * D_];
__device__ float g_v[(size_t)B_ * H_ * N_ * D_];
__device__ float g_att[(size_t)M_ * E_];           // [b*n][h*d] recombined heads
__device__ int   g_mflag[B_ * NT_ * NT_];          // 1 = tile all-nonzero (skip mask)

__device__ __forceinline__ float neg_inf() { return __int_as_float(0xff800000); }

// round-to-nearest tf32, result kept as float bit pattern (low 13 mantissa bits zero)
__device__ __forceinline__ float f2tf(float x) {
    uint32_t r;
    asm("cvt.rna.tf32.f32 %0, %1;" : "=r"(r) : "f"(x));
    return __uint_as_float(r);
}

// m16n8k8 tf32 mma: c += a * b  (a: 4 regs, b: 2 regs, c: 4 f32)
__device__ __forceinline__ void mma8(float* c, const uint32_t* a, const uint32_t* b) {
    asm volatile(
        "mma.sync.aligned.m16n8k8.row.col.f32.tf32.tf32.f32 "
        "{%0,%1,%2,%3}, {%4,%5,%6,%7}, {%8,%9}, {%0,%1,%2,%3};\n"
        : "+f"(c[0]), "+f"(c[1]), "+f"(c[2]), "+f"(c[3])
        : "r"(a[0]), "r"(a[1]), "r"(a[2]), "r"(a[3]), "r"(b[0]), "r"(b[1]));
}

// ---------------------------------------------------------------------------
// Mask preprocessing: one flag per (b, q-tile, kv-tile): 1 if the whole 64x64
// tile is nonzero (attention may skip mask loads). Exact, so correct for any mask.
// ---------------------------------------------------------------------------
__global__ __launch_bounds__(256)
void mask_flags(const int* __restrict__ mask)
{
    const int kvt = blockIdx.x, qt = blockIdx.y, b = blockIdx.z;
    const int tid = threadIdx.x;
    const int r = tid >> 2, c0 = (tid & 3) * 16;
    const int* base = mask + (size_t)b * N_ * N_ + (size_t)(qt * 64 + r) * N_ + kvt * 64 + c0;
    bool ok = true;
    #pragma unroll
    for (int i = 0; i < 4; i++) {
        int4 m = *reinterpret_cast<const int4*>(base + i * 4);
        ok &= (m.x != 0) & (m.y != 0) & (m.z != 0) & (m.w != 0);
    }
    int all = __syncthreads_and((int)ok);
    if (tid == 0) g_mflag[(b * NT_ + qt) * NT_ + kvt] = all;
}

// ---------------------------------------------------------------------------
// Shared GEMM body: Y-tile = X-tile @ W-tile^T with 3xTF32 (hi/lo split).
// Block 128x64, BK=32, 256 thr = 8 warps (4m x 2n), warp tile 32x32.
// Smem stride 36 -> conflict-free fragment LDS.
// ---------------------------------------------------------------------------
__device__ __forceinline__ void gemm_core(const float* __restrict__ X,
                                          const float* __restrict__ W,
                                          float* sm, int m0, int n0,
                                          float acc[2][4][4])
{
    float* Xh = sm;                    // [128][36]
    float* Xl = Xh + 128 * 36;
    float* Wh = Xl + 128 * 36;         // [64][36]
    float* Wl = Wh + 64 * 36;

    const int tid = threadIdx.x;
    const int warp = tid >> 5, lane = tid & 31;
    const int g = lane >> 2, tg = lane & 3;
    const int wm = warp >> 1, wn = warp & 1;
    const int xr = tid >> 1, xk0 = (tid & 1) * 16;
    const int wr = tid >> 2, wk0 = (tid & 3) * 8;

    for (int kt = 0; kt < E_; kt += 32) {
        __syncthreads();
        #pragma unroll
        for (int i = 0; i < 4; i++) {
            float4 v = *reinterpret_cast<const float4*>(X + (size_t)(m0 + xr) * E_ + kt + xk0 + i * 4);
            float h0 = f2tf(v.x), h1 = f2tf(v.y), h2 = f2tf(v.z), h3 = f2tf(v.w);
            *reinterpret_cast<float4*>(&Xh[xr * 36 + xk0 + i * 4]) = make_float4(h0, h1, h2, h3);
            *reinterpret_cast<float4*>(&Xl[xr * 36 + xk0 + i * 4]) =
                make_float4(f2tf(v.x - h0), f2tf(v.y - h1), f2tf(v.z - h2), f2tf(v.w - h3));
        }
        #pragma unroll
        for (int i = 0; i < 2; i++) {
            float4 v = *reinterpret_cast<const float4*>(W + (size_t)(n0 + wr) * E_ + kt + wk0 + i * 4);
            float h0 = f2tf(v.x), h1 = f2tf(v.y), h2 = f2tf(v.z), h3 = f2tf(v.w);
            *reinterpret_cast<float4*>(&Wh[wr * 36 + wk0 + i * 4]) = make_float4(h0, h1, h2, h3);
            *reinterpret_cast<float4*>(&Wl[wr * 36 + wk0 + i * 4]) =
                make_float4(f2tf(v.x - h0), f2tf(v.y - h1), f2tf(v.z - h2), f2tf(v.w - h3));
        }
        __syncthreads();

        #pragma unroll
        for (int ks = 0; ks < 4; ks++) {
            const int k0 = ks * 8;
            uint32_t Ah[2][4], Al[2][4], Bh[4][2], Bl[4][2];
            #pragma unroll
            for (int mt = 0; mt < 2; mt++) {
                const int rb = (wm * 32 + mt * 16) * 36 + k0;
                Ah[mt][0] = __float_as_uint(Xh[rb + g * 36 + tg]);
                Ah[mt][1] = __float_as_uint(Xh[rb + (g + 8) * 36 + tg]);
                Ah[mt][2] = __float_as_uint(Xh[rb + g * 36 + tg + 4]);
                Ah[mt][3] = __float_as_uint(Xh[rb + (g + 8) * 36 + tg + 4]);
                Al[mt][0] = __float_as_uint(Xl[rb + g * 36 + tg]);
                Al[mt][1] = __float_as_uint(Xl[rb + (g + 8) * 36 + tg]);
                Al[mt][2] = __float_as_uint(Xl[rb + g * 36 + tg + 4]);
                Al[mt][3] = __float_as_uint(Xl[rb + (g + 8) * 36 + tg + 4]);
            }
            #pragma unroll
            for (int nt = 0; nt < 4; nt++) {
                const int rb = (wn * 32 + nt * 8 + g) * 36 + k0;
                Bh[nt][0] = __float_as_uint(Wh[rb + tg]);
                Bh[nt][1] = __float_as_uint(Wh[rb + tg + 4]);
                Bl[nt][0] = __float_as_uint(Wl[rb + tg]);
                Bl[nt][1] = __float_as_uint(Wl[rb + tg + 4]);
            }
            #pragma unroll
            for (int mt = 0; mt < 2; mt++)
                #pragma unroll
                for (int nt = 0; nt < 4; nt++) {
                    mma8(acc[mt][nt], Ah[mt], Bh[nt]);   // hi*hi
                    mma8(acc[mt][nt], Ah[mt], Bl[nt]);   // hi*lo
                    mma8(acc[mt][nt], Al[mt], Bh[nt]);   // lo*hi
                }
        }
    }
}

// QKV projections fused in one launch: blockIdx.z selects (X, W, target).
__global__ __launch_bounds__(256)
void gemm_qkv(const float* __restrict__ Qi, const float* __restrict__ Ki,
              const float* __restrict__ Vi, const float* __restrict__ Wq,
              const float* __restrict__ Wk, const float* __restrict__ Wv)
{
    extern __shared__ float sm[];
    const int z = blockIdx.z;
    const float* X = (z == 0) ? Qi : (z == 1) ? Ki : Vi;
    const float* W = (z == 0) ? Wq : (z == 1) ? Wk : Wv;
    float* Y = (z == 0) ? g_q : (z == 1) ? g_k : g_v;

    const int m0 = blockIdx.y * 128, n0 = blockIdx.x * 64;
    float acc[2][4][4] = {};
    gemm_core(X, W, sm, m0, n0, acc);

    const int tid = threadIdx.x;
    const int warp = tid >> 5, lane = tid & 31;
    const int g = lane >> 2, tg = lane & 3;
    const int wm = warp >> 1, wn = warp & 1;
    const int h = blockIdx.x;              // BN=64 == head dim
    #pragma unroll
    for (int mt = 0; mt < 2; mt++) {
        #pragma unroll
        for (int nt = 0; nt < 4; nt++) {
            const int dd = wn * 32 + nt * 8 + 2 * tg;
            int m = m0 + wm * 32 + mt * 16 + g;
            int b = m >> 11, n = m & (N_ - 1);
            *reinterpret_cast<float2*>(&Y[((size_t)((b * H_ + h) * N_ + n)) * D_ + dd]) =
                make_float2(acc[mt][nt][0], acc[mt][nt][1]);
            m += 8; b = m >> 11; n = m & (N_ - 1);
            *reinterpret_cast<float2*>(&Y[((size_t)((b * H_ + h) * N_ + n)) * D_ + dd]) =
                make_float2(acc[mt][nt][2], acc[mt][nt][3]);
        }
    }
}

// Output projection: g_att @ Wo^T + bo -> out
__global__ __launch_bounds__(256)
void gemm_out(const float* __restrict__ Wo, const float* __restrict__ bias,
              float* __restrict__ Yext)
{
    extern __shared__ float sm[];
    const int m0 = blockIdx.y * 128, n0 = blockIdx.x * 64;
    float acc[2][4][4] = {};
    gemm_core(g_att, Wo, sm, m0, n0, acc);

    const int tid = threadIdx.x;
    const int warp = tid >> 5, lane = tid & 31;
    const int g = lane >> 2, tg = lane & 3;
    const int wm = warp >> 1, wn = warp & 1;
    #pragma unroll
    for (int mt = 0; mt < 2; mt++) {
        #pragma unroll
        for (int nt = 0; nt < 4; nt++) {
            const int o = n0 + wn * 32 + nt * 8 + 2 * tg;
            float2 bb = *reinterpret_cast<const float2*>(bias + o);
            const int m = m0 + wm * 32 + mt * 16 + g;
            *reinterpret_cast<float2*>(&Yext[(size_t)m * E_ + o]) =
                make_float2(acc[mt][nt][0] + bb.x, acc[mt][nt][1] + bb.y);
            *reinterpret_cast<float2*>(&Yext[(size_t)(m + 8) * E_ + o]) =
                make_float2(acc[mt][nt][2] + bb.x, acc[mt][nt][3] + bb.y);
        }
    }
}

// ---------------------------------------------------------------------------
// Flash attention, tf32 mma. Block = (h, 64 q rows, b), 4 warps x 16 rows.
// Q a-fragments hoisted to registers (loop-invariant); the Qs smem region is
// then reused as Ps (both touch only warp-private rows -> alias is safe).
// 1/tau folded into Q at load (rna AFTER scale). Mask applied only when the
// precomputed tile flag says the tile has zeros.
// Smem 52224 B -> 4 blocks/SM (16 warps), __launch_bounds__(128,4).
// ---------------------------------------------------------------------------
__global__ __launch_bounds__(128, 4)
void attn_tc(const int* __restrict__ mask, const float* __restrict__ taup)
{
    extern __shared__ float sm[];
    float* QPs = sm;                 // [64][68]: Q tf32, later P tf32 (warp-private rows)
    float* Ks  = QPs + 64 * 68;      // [64 kv][68 d]
    float* Vs  = Ks + 64 * 68;       // [64 kv][68 d]

    const int h = blockIdx.x, qt = blockIdx.y, b = blockIdx.z;
    const int tid = threadIdx.x;
    const int warp = tid >> 5, lane = tid & 31;
    const int g = lane >> 2, tg = lane & 3;
    const int q0 = qt * 64;
    const float inv_tau = 1.0f / __ldg(taup);

    const size_t bh = (size_t)(b * H_ + h) * N_ * D_;
    const float* qbase = g_q + bh;
    const float* kbase = g_k + bh;
    const float* vbase = g_v + bh;
    const int* mbase = mask + (size_t)b * N_ * N_;
    const int* fbase = g_mflag + (b * NT_ + qt) * NT_;

    // Load Q tile scaled by 1/tau, tf32-rounded after scaling
    {
        const int r = tid >> 1, c0 = (tid & 1) * 32;
        #pragma unroll
        for (int i = 0; i < 8; i++) {
            float4 v = *reinterpret_cast<const float4*>(qbase + (size_t)(q0 + r) * D_ + c0 + i * 4);
            *reinterpret_cast<float4*>(&QPs[r * 68 + c0 + i * 4]) =
                make_float4(f2tf(v.x * inv_tau), f2tf(v.y * inv_tau),
                            f2tf(v.z * inv_tau), f2tf(v.w * inv_tau));
        }
    }
    __syncthreads();

    // Hoist Q a-frags (warp-private rows of QPs)
    uint32_t q_a[8][4];
    #pragma unroll
    for (int kp = 0; kp < 8; kp++) {
        const int qb = (warp * 16) * 68 + kp * 8;
        q_a[kp][0] = __float_as_uint(QPs[qb + g * 68 + tg]);
        q_a[kp][1] = __float_as_uint(QPs[qb + (g + 8) * 68 + tg]);
        q_a[kp][2] = __float_as_uint(QPs[qb + g * 68 + tg + 4]);
        q_a[kp][3] = __float_as_uint(QPs[qb + (g + 8) * 68 + tg + 4]);
    }

    float o[8][4] = {};                           // O c-frags: [d-tile][c]
    float mr0 = neg_inf(), mr1 = neg_inf();       // running max (rows g, g+8)
    float lr0 = 0.0f, lr1 = 0.0f;                 // running sum

    const int qrow = q0 + warp * 16 + g;          // global q row for c0/c1

    for (int kvt = 0; kvt < NT_; kvt++) {
        const int kv0 = kvt * 64;
        const int clean = __ldg(fbase + kvt);
        __syncthreads();   // prior iter's Vs reads done
        // Load K,V tiles (tf32)
        {
            const int r = tid >> 1, c0 = (tid & 1) * 32;
            #pragma unroll
            for (int i = 0; i < 8; i++) {
                float4 kv = *reinterpret_cast<const float4*>(kbase + (size_t)(kv0 + r) * D_ + c0 + i * 4);
                *reinterpret_cast<float4*>(&Ks[r * 68 + c0 + i * 4]) =
                    make_float4(f2tf(kv.x), f2tf(kv.y), f2tf(kv.z), f2tf(kv.w));
                float4 vv = *reinterpret_cast<const float4*>(vbase + (size_t)(kv0 + r) * D_ + c0 + i * 4);
                *reinterpret_cast<float4*>(&Vs[r * 68 + c0 + i * 4]) =
                    make_float4(f2tf(vv.x), f2tf(vv.y), f2tf(vv.z), f2tf(vv.w));
            }
        }
        __syncthreads();

        // S = (Q/tau) @ K^T : warp computes 16 x 64
        float s[8][4] = {};
        #pragma unroll
        for (int kp = 0; kp < 8; kp++) {
            #pragma unroll
            for (int nt = 0; nt < 8; nt++) {
                uint32_t bfr[2];
                const int kb = (nt * 8 + g) * 68 + kp * 8 + tg;
                bfr[0] = __float_as_uint(Ks[kb]);
                bfr[1] = __float_as_uint(Ks[kb + 4]);
                mma8(s[nt], q_a[kp], bfr);
            }
        }

        // mask only when the tile has zeros
        if (!clean) {
            #pragma unroll
            for (int nt = 0; nt < 8; nt++) {
                const int col = kv0 + nt * 8 + 2 * tg;
                int2 mA = *reinterpret_cast<const int2*>(mbase + (size_t)qrow * N_ + col);
                int2 mB = *reinterpret_cast<const int2*>(mbase + (size_t)(qrow + 8) * N_ + col);
                if (!mA.x) s[nt][0] = neg_inf();
                if (!mA.y) s[nt][1] = neg_inf();
                if (!mB.x) s[nt][2] = neg_inf();
                if (!mB.y) s[nt][3] = neg_inf();
            }
        }

        // online softmax (rows g and g+8)
        float mx0 = neg_inf(), mx1 = neg_inf();
        #pragma unroll
        for (int nt = 0; nt < 8; nt++) {
            mx0 = fmaxf(mx0, fmaxf(s[nt][0], s[nt][1]));
            mx1 = fmaxf(mx1, fmaxf(s[nt][2], s[nt][3]));
        }
        mx0 = fmaxf(mx0, __shfl_xor_sync(0xffffffffu, mx0, 1));
        mx0 = fmaxf(mx0, __shfl_xor_sync(0xffffffffu, mx0, 2));
        mx1 = fmaxf(mx1, __shfl_xor_sync(0xffffffffu, mx1, 1));
        mx1 = fmaxf(mx1, __shfl_xor_sync(0xffffffffu, mx1, 2));
        const float mn0 = fmaxf(mr0, mx0), mn1 = fmaxf(mr1, mx1);
        // fmaxf(x, -80) absorbs -inf edge cases (fully masked rows) into exp->~0
        const float sc0 = __expf(fmaxf(mr0 - mn0, -80.0f));
        const float sc1 = __expf(fmaxf(mr1 - mn1, -80.0f));
        float sum0 = 0.0f, sum1 = 0.0f;
        #pragma unroll
        for (int nt = 0; nt < 8; nt++) {
            float p0 = __expf(fmaxf(s[nt][0] - mn0, -80.0f));
            float p1 = __expf(fmaxf(s[nt][1] - mn0, -80.0f));
            float p2 = __expf(fmaxf(s[nt][2] - mn1, -80.0f));
            float p3 = __expf(fmaxf(s[nt][3] - mn1, -80.0f));
            s[nt][0] = p0; s[nt][1] = p1; s[nt][2] = p2; s[nt][3] = p3;
            sum0 += p0 + p1; sum1 += p2 + p3;
        }
        sum0 += __shfl_xor_sync(0xffffffffu, sum0, 1);
        sum0 += __shfl_xor_sync(0xffffffffu, sum0, 2);
        sum1 += __shfl_xor_sync(0xffffffffu, sum1, 1);
        sum1 += __shfl_xor_sync(0xffffffffu, sum1, 2);
        lr0 = lr0 * sc0 + sum0; lr1 = lr1 * sc1 + sum1;
        mr0 = mn0; mr1 = mn1;

        // rescale O
        #pragma unroll
        for (int dt = 0; dt < 8; dt++) {
            o[dt][0] *= sc0; o[dt][1] *= sc0;
            o[dt][2] *= sc1; o[dt][3] *= sc1;
        }

        // P -> smem (reusing QPs; warp-private rows), c-frag -> a-frag fix-up
        #pragma unroll
        for (int nt = 0; nt < 8; nt++) {
            const int pb = (warp * 16 + g) * 68 + nt * 8 + 2 * tg;
            *reinterpret_cast<float2*>(&QPs[pb]) = make_float2(f2tf(s[nt][0]), f2tf(s[nt][1]));
            *reinterpret_cast<float2*>(&QPs[pb + 8 * 68]) = make_float2(f2tf(s[nt][2]), f2tf(s[nt][3]));
        }
        __syncwarp();

        // O += P @ V
        #pragma unroll
        for (int kp = 0; kp < 8; kp++) {
            uint32_t a[4];
            const int pb = (warp * 16) * 68 + kp * 8;
            a[0] = __float_as_uint(QPs[pb + g * 68 + tg]);
            a[1] = __float_as_uint(QPs[pb + (g + 8) * 68 + tg]);
            a[2] = __float_as_uint(QPs[pb + g * 68 + tg + 4]);
            a[3] = __float_as_uint(QPs[pb + (g + 8) * 68 + tg + 4]);
            #pragma unroll
            for (int dt = 0; dt < 8; dt++) {
                uint32_t bfr[2];
                const int vb = (kp * 8 + tg) * 68 + dt * 8 + g;
                bfr[0] = __float_as_uint(Vs[vb]);
                bfr[1] = __float_as_uint(Vs[vb + 4 * 68]);
                mma8(o[dt], a, bfr);
            }
        }
        __syncwarp();  // PV reads done before next iteration overwrites tiles
    }

    // Epilogue: normalize and recombine heads
    const float il0 = 1.0f / lr0, il1 = 1.0f / lr1;
    #pragma unroll
    for (int dt = 0; dt < 8; dt++) {
        const int dd = h * 64 + dt * 8 + 2 * tg;
        *reinterpret_cast<float2*>(&g_att[(size_t)(b * N_ + qrow) * E_ + dd]) =
            make_float2(o[dt][0] * il0, o[dt][1] * il0);
        *reinterpret_cast<float2*>(&g_att[(size_t)(b * N_ + qrow + 8) * E_ + dd]) =
            make_float2(o[dt][2] * il1, o[dt][3] * il1);
    }
}

// ---------------------------------------------------------------------------
extern "C" void kernel_launch(void* const* d_in, const int* in_sizes, int n_in,
                              void* d_out, int out_size)
{
    const float* Q    = (const float*)d_in[0];
    const float* K    = (const float*)d_in[1];
    const float* V    = (const float*)d_in[2];
    const int*   mask = (const int*)  d_in[3];
    const float* Wq   = (const float*)d_in[4];
    const float* Wk   = (const float*)d_in[5];
    const float* Wv   = (const float*)d_in[6];
    const float* Wo   = (const float*)d_in[7];
    const float* bo   = (const float*)d_in[8];
    const float* tau  = (const float*)d_in[9];
    float* out = (float*)d_out;

    const int gemm_smem = (128 * 36 * 2 + 64 * 36 * 2) * (int)sizeof(float);  // 55296
    const int attn_smem = 3 * 64 * 68 * (int)sizeof(float);                   // 52224

    cudaFuncSetAttribute(gemm_qkv, cudaFuncAttributeMaxDynamicSharedMemorySize, gemm_smem);
    cudaFuncSetAttribute(gemm_out, cudaFuncAttributeMaxDynamicSharedMemorySize, gemm_smem);
    cudaFuncSetAttribute(attn_tc, cudaFuncAttributeMaxDynamicSharedMemorySize, attn_smem);

    mask_flags<<<dim3(NT_, NT_, B_), 256>>>(mask);

    gemm_qkv<<<dim3(E_ / 64, M_ / 128, 3), 256, gemm_smem>>>(Q, K, V, Wq, Wk, Wv);

    // grid.x = heads (fastest) so the 8 heads sharing a mask tile are adjacent -> L2 reuse
    attn_tc<<<dim3(H_, N_ / 64, B_), 128, attn_smem>>>(mask, tau);

    gemm_out<<<dim3(E_ / 64, M_ / 128), 256, gemm_smem>>>(Wo, bo, out);
}

// round 5
// speedup vs baseline: 2.2241x; 1.4504x over previous
#include <cuda_runtime.h>
#include <cstdint>
#include <cstddef>

// Problem constants
constexpr int B_ = 8;
constexpr int N_ = 2048;
constexpr int E_ = 512;
constexpr int H_ = 8;
constexpr int D_ = 64;
constexpr int M_ = B_ * N_;   // 16384 rows
constexpr int NT_ = N_ / 64;  // 32 64-row tiles (mask-flag granularity)
constexpr int KT_ = 32;       // attention kv-tile rows
constexpr int NKT_ = N_ / KT_;// 64 kv tiles
constexpr int ST_ = 68;       // smem row stride (floats); 68*4B % 16 == 0

// Scratch (device globals: allocation-free per harness rules)
__device__ float g_q[(size_t)B_ * H_ * N_ * D_];   // [b][h][n][d], pre-scaled by log2e/tau, tf32
__device__ float g_k[(size_t)B_ * H_ * N_ * D_];   // tf32-rounded
__device__ float g_v[(size_t)B_ * H_ * N_ * D_];   // tf32-rounded
__device__ float g_att[(size_t)M_ * E_];           // [b*n][h*d] recombined heads
__device__ int   g_mflag[B_ * NT_ * NT_];          // 1 = 64x64 tile all-nonzero

__device__ __forceinline__ float neg_inf() { return __int_as_float(0xff800000); }

__device__ __forceinline__ float f2tf(float x) {
    uint32_t r;
    asm("cvt.rna.tf32.f32 %0, %1;" : "=r"(r) : "f"(x));
    return __uint_as_float(r);
}

__device__ __forceinline__ float fexp2(float x) {
    float y;
    asm("ex2.approx.ftz.f32 %0, %1;" : "=f"(y) : "f"(x));
    return y;
}

// m16n8k8 tf32 mma: c += a * b
__device__ __forceinline__ void mma8(float* c, const uint32_t* a, const uint32_t* b) {
    asm volatile(
        "mma.sync.aligned.m16n8k8.row.col.f32.tf32.tf32.f32 "
        "{%0,%1,%2,%3}, {%4,%5,%6,%7}, {%8,%9}, {%0,%1,%2,%3};\n"
        : "+f"(c[0]), "+f"(c[1]), "+f"(c[2]), "+f"(c[3])
        : "r"(a[0]), "r"(a[1]), "r"(a[2]), "r"(a[3]), "r"(b[0]), "r"(b[1]));
}

// cp.async helpers
__device__ __forceinline__ void cp16(const float* smem_dst, const float* gmem_src) {
    uint32_t s = (uint32_t)__cvta_generic_to_shared(smem_dst);
    asm volatile("cp.async.ca.shared.global [%0], [%1], 16;" :: "r"(s), "l"(gmem_src));
}
__device__ __forceinline__ void cp_commit() { asm volatile("cp.async.commit_group;"); }
__device__ __forceinline__ void cp_wait0()  { asm volatile("cp.async.wait_group 0;" ::: "memory"); }

// ---------------------------------------------------------------------------
// Mask preprocessing: one flag per (b, 64-row q tile, 64-col kv tile).
// ---------------------------------------------------------------------------
__global__ __launch_bounds__(256)
void mask_flags(const int* __restrict__ mask)
{
    const int kvt = blockIdx.x, qt = blockIdx.y, b = blockIdx.z;
    const int tid = threadIdx.x;
    const int r = tid >> 2, c0 = (tid & 3) * 16;
    const int* base = mask + (size_t)b * N_ * N_ + (size_t)(qt * 64 + r) * N_ + kvt * 64 + c0;
    bool ok = true;
    #pragma unroll
    for (int i = 0; i < 4; i++) {
        int4 m = *reinterpret_cast<const int4*>(base + i * 4);
        ok &= (m.x != 0) & (m.y != 0) & (m.z != 0) & (m.w != 0);
    }
    int all = __syncthreads_and((int)ok);
    if (tid == 0) g_mflag[(b * NT_ + qt) * NT_ + kvt] = all;
}

// ---------------------------------------------------------------------------
// Shared GEMM body: 3xTF32 (hi/lo split). Block 128x64, BK=32, 8 warps.
// ---------------------------------------------------------------------------
__device__ __forceinline__ void gemm_core(const float* __restrict__ X,
                                          const float* __restrict__ W,
                                          float* sm, int m0, int n0,
                                          float acc[2][4][4])
{
    float* Xh = sm;                    // [128][36]
    float* Xl = Xh + 128 * 36;
    float* Wh = Xl + 128 * 36;         // [64][36]
    float* Wl = Wh + 64 * 36;

    const int tid = threadIdx.x;
    const int warp = tid >> 5, lane = tid & 31;
    const int g = lane >> 2, tg = lane & 3;
    const int wm = warp >> 1, wn = warp & 1;
    const int xr = tid >> 1, xk0 = (tid & 1) * 16;
    const int wr = tid >> 2, wk0 = (tid & 3) * 8;

    for (int kt = 0; kt < E_; kt += 32) {
        __syncthreads();
        #pragma unroll
        for (int i = 0; i < 4; i++) {
            float4 v = *reinterpret_cast<const float4*>(X + (size_t)(m0 + xr) * E_ + kt + xk0 + i * 4);
            float h0 = f2tf(v.x), h1 = f2tf(v.y), h2 = f2tf(v.z), h3 = f2tf(v.w);
            *reinterpret_cast<float4*>(&Xh[xr * 36 + xk0 + i * 4]) = make_float4(h0, h1, h2, h3);
            *reinterpret_cast<float4*>(&Xl[xr * 36 + xk0 + i * 4]) =
                make_float4(f2tf(v.x - h0), f2tf(v.y - h1), f2tf(v.z - h2), f2tf(v.w - h3));
        }
        #pragma unroll
        for (int i = 0; i < 2; i++) {
            float4 v = *reinterpret_cast<const float4*>(W + (size_t)(n0 + wr) * E_ + kt + wk0 + i * 4);
            float h0 = f2tf(v.x), h1 = f2tf(v.y), h2 = f2tf(v.z), h3 = f2tf(v.w);
            *reinterpret_cast<float4*>(&Wh[wr * 36 + wk0 + i * 4]) = make_float4(h0, h1, h2, h3);
            *reinterpret_cast<float4*>(&Wl[wr * 36 + wk0 + i * 4]) =
                make_float4(f2tf(v.x - h0), f2tf(v.y - h1), f2tf(v.z - h2), f2tf(v.w - h3));
        }
        __syncthreads();

        #pragma unroll
        for (int ks = 0; ks < 4; ks++) {
            const int k0 = ks * 8;
            uint32_t Ah[2][4], Al[2][4], Bh[4][2], Bl[4][2];
            #pragma unroll
            for (int mt = 0; mt < 2; mt++) {
                const int rb = (wm * 32 + mt * 16) * 36 + k0;
                Ah[mt][0] = __float_as_uint(Xh[rb + g * 36 + tg]);
                Ah[mt][1] = __float_as_uint(Xh[rb + (g + 8) * 36 + tg]);
                Ah[mt][2] = __float_as_uint(Xh[rb + g * 36 + tg + 4]);
                Ah[mt][3] = __float_as_uint(Xh[rb + (g + 8) * 36 + tg + 4]);
                Al[mt][0] = __float_as_uint(Xl[rb + g * 36 + tg]);
                Al[mt][1] = __float_as_uint(Xl[rb + (g + 8) * 36 + tg]);
                Al[mt][2] = __float_as_uint(Xl[rb + g * 36 + tg + 4]);
                Al[mt][3] = __float_as_uint(Xl[rb + (g + 8) * 36 + tg + 4]);
            }
            #pragma unroll
            for (int nt = 0; nt < 4; nt++) {
                const int rb = (wn * 32 + nt * 8 + g) * 36 + k0;
                Bh[nt][0] = __float_as_uint(Wh[rb + tg]);
                Bh[nt][1] = __float_as_uint(Wh[rb + tg + 4]);
                Bl[nt][0] = __float_as_uint(Wl[rb + tg]);
                Bl[nt][1] = __float_as_uint(Wl[rb + tg + 4]);
            }
            #pragma unroll
            for (int mt = 0; mt < 2; mt++)
                #pragma unroll
                for (int nt = 0; nt < 4; nt++) {
                    mma8(acc[mt][nt], Ah[mt], Bh[nt]);
                    mma8(acc[mt][nt], Ah[mt], Bl[nt]);
                    mma8(acc[mt][nt], Al[mt], Bh[nt]);
                }
        }
    }
}

// QKV projections fused; outputs pre-formatted for attention:
//  z=0 (Q): scaled by log2e/tau, tf32-rounded.  z=1 (K), z=2 (V): tf32-rounded.
__global__ __launch_bounds__(256)
void gemm_qkv(const float* __restrict__ Qi, const float* __restrict__ Ki,
              const float* __restrict__ Vi, const float* __restrict__ Wq,
              const float* __restrict__ Wk, const float* __restrict__ Wv,
              const float* __restrict__ taup)
{
    extern __shared__ float sm[];
    const int z = blockIdx.z;
    const float* X = (z == 0) ? Qi : (z == 1) ? Ki : Vi;
    const float* W = (z == 0) ? Wq : (z == 1) ? Wk : Wv;
    float* Y = (z == 0) ? g_q : (z == 1) ? g_k : g_v;
    const float scl = (z == 0) ? (1.4426950408889634f / __ldg(taup)) : 1.0f;

    const int m0 = blockIdx.y * 128, n0 = blockIdx.x * 64;
    float acc[2][4][4] = {};
    gemm_core(X, W, sm, m0, n0, acc);

    const int tid = threadIdx.x;
    const int warp = tid >> 5, lane = tid & 31;
    const int g = lane >> 2, tg = lane & 3;
    const int wm = warp >> 1, wn = warp & 1;
    const int h = blockIdx.x;              // BN=64 == head dim
    #pragma unroll
    for (int mt = 0; mt < 2; mt++) {
        #pragma unroll
        for (int nt = 0; nt < 4; nt++) {
            const int dd = wn * 32 + nt * 8 + 2 * tg;
            int m = m0 + wm * 32 + mt * 16 + g;
            int b = m >> 11, n = m & (N_ - 1);
            *reinterpret_cast<float2*>(&Y[((size_t)((b * H_ + h) * N_ + n)) * D_ + dd]) =
                make_float2(f2tf(acc[mt][nt][0] * scl), f2tf(acc[mt][nt][1] * scl));
            m += 8; b = m >> 11; n = m & (N_ - 1);
            *reinterpret_cast<float2*>(&Y[((size_t)((b * H_ + h) * N_ + n)) * D_ + dd]) =
                make_float2(f2tf(acc[mt][nt][2] * scl), f2tf(acc[mt][nt][3] * scl));
        }
    }
}

// Output projection: g_att @ Wo^T + bo -> out
__global__ __launch_bounds__(256)
void gemm_out(const float* __restrict__ Wo, const float* __restrict__ bias,
              float* __restrict__ Yext)
{
    extern __shared__ float sm[];
    const int m0 = blockIdx.y * 128, n0 = blockIdx.x * 64;
    float acc[2][4][4] = {};
    gemm_core(g_att, Wo, sm, m0, n0, acc);

    const int tid = threadIdx.x;
    const int warp = tid >> 5, lane = tid & 31;
    const int g = lane >> 2, tg = lane & 3;
    const int wm = warp >> 1, wn = warp & 1;
    #pragma unroll
    for (int mt = 0; mt < 2; mt++) {
        #pragma unroll
        for (int nt = 0; nt < 4; nt++) {
            const int o = n0 + wn * 32 + nt * 8 + 2 * tg;
            float2 bb = *reinterpret_cast<const float2*>(bias + o);
            const int m = m0 + wm * 32 + mt * 16 + g;
            *reinterpret_cast<float2*>(&Yext[(size_t)m * E_ + o]) =
                make_float2(acc[mt][nt][0] + bb.x, acc[mt][nt][1] + bb.y);
            *reinterpret_cast<float2*>(&Yext[(size_t)(m + 8) * E_ + o]) =
                make_float2(acc[mt][nt][2] + bb.x, acc[mt][nt][3] + bb.y);
        }
    }
}

// ---------------------------------------------------------------------------
// Flash attention v3: tf32 mma, cp.async double-buffered kv tiles of 32 rows.
// Block = (h, 64 q rows, b), 4 warps x 16 q rows. Q/K/V arrive pre-rounded
// (Q also pre-scaled by log2e/tau) -> zero conversions in the load path.
// Smem = 2 x (K 32x68 + V 32x68) = 34816 B -> 5 blocks/SM (20 warps).
// P c-frag -> a-frag via quad shfls (no smem round trip). Softmax in log2.
// ---------------------------------------------------------------------------
__global__ __launch_bounds__(128, 5)
void attn_tc(const int* __restrict__ mask)
{
    __shared__ float sm[4 * KT_ * ST_];   // [buf0: K,V][buf1: K,V]; Q staged here first

    const int h = blockIdx.x, qt = blockIdx.y, b = blockIdx.z;
    const int tid = threadIdx.x;
    const int warp = tid >> 5, lane = tid & 31;
    const int g = lane >> 2, tg = lane & 3;
    const int q0 = qt * 64;

    const size_t bh = (size_t)(b * H_ + h) * N_ * D_;
    const float* qbase = g_q + bh;
    const float* kbase = g_k + bh;
    const float* vbase = g_v + bh;
    const int* mbase = mask + (size_t)b * N_ * N_;
    const int* fbase = g_mflag + (b * NT_ + qt) * NT_;

    // ---- Stage Q (64x64, already scaled+tf32) through the buffer region ----
    {
        #pragma unroll
        for (int i = 0; i < 8; i++) {
            int idx = tid + i * 128;             // 0..1023
            int r = idx >> 4, c = (idx & 15) * 4;
            cp16(&sm[r * ST_ + c], qbase + (size_t)(q0 + r) * D_ + c);
        }
        cp_commit(); cp_wait0();
        __syncthreads();
    }

    // Hoist Q a-frags
    uint32_t q_a[8][4];
    #pragma unroll
    for (int kp = 0; kp < 8; kp++) {
        const int qb = (warp * 16) * ST_ + kp * 8;
        q_a[kp][0] = __float_as_uint(sm[qb + g * ST_ + tg]);
        q_a[kp][1] = __float_as_uint(sm[qb + (g + 8) * ST_ + tg]);
        q_a[kp][2] = __float_as_uint(sm[qb + g * ST_ + tg + 4]);
        q_a[kp][3] = __float_as_uint(sm[qb + (g + 8) * ST_ + tg + 4]);
    }
    __syncthreads();   // Q staging region free for kv buffers

    // ---- Prefetch kv tile 0 into buf 0 ----
    {
        #pragma unroll
        for (int i = 0; i < 4; i++) {
            int idx = tid + i * 128;             // 0..511
            int r = idx >> 4, c = (idx & 15) * 4;
            cp16(&sm[r * ST_ + c],             kbase + (size_t)r * D_ + c);
            cp16(&sm[2176 + r * ST_ + c],      vbase + (size_t)r * D_ + c);
        }
        cp_commit();
    }

    float o[8][4] = {};
    float mr0 = neg_inf(), mr1 = neg_inf();
    float lr0 = 0.0f, lr1 = 0.0f;
    const int qrow = q0 + warp * 16 + g;

    for (int t = 0; t < NKT_; t++) {
        cp_wait0();
        __syncthreads();   // tile t resident; all warps done with buf[(t+1)&1]

        // prefetch t+1 into the other buffer (overlaps this tile's compute)
        if (t + 1 < NKT_) {
            const float* kb2 = kbase + (size_t)(t + 1) * KT_ * D_;
            const float* vb2 = vbase + (size_t)(t + 1) * KT_ * D_;
            float* dst = sm + ((t + 1) & 1) * 4352;
            #pragma unroll
            for (int i = 0; i < 4; i++) {
                int idx = tid + i * 128;
                int r = idx >> 4, c = (idx & 15) * 4;
                cp16(&dst[r * ST_ + c],        kb2 + (size_t)r * D_ + c);
                cp16(&dst[2176 + r * ST_ + c], vb2 + (size_t)r * D_ + c);
            }
            cp_commit();
        }

        const float* Kc = sm + (t & 1) * 4352;
        const float* Vc = Kc + 2176;
        const int kv0 = t * KT_;
        const int clean = __ldg(fbase + (t >> 1));

        // S = Q @ K^T (log2 units): warp computes 16 x 32
        float s[4][4] = {};
        #pragma unroll
        for (int kp = 0; kp < 8; kp++) {
            #pragma unroll
            for (int nt = 0; nt < 4; nt++) {
                uint32_t bfr[2];
                const int kb = (nt * 8 + g) * ST_ + kp * 8 + tg;
                bfr[0] = __float_as_uint(Kc[kb]);
                bfr[1] = __float_as_uint(Kc[kb + 4]);
                mma8(s[nt], q_a[kp], bfr);
            }
        }

        if (!clean) {
            #pragma unroll
            for (int nt = 0; nt < 4; nt++) {
                const int col = kv0 + nt * 8 + 2 * tg;
                int2 mA = *reinterpret_cast<const int2*>(mbase + (size_t)qrow * N_ + col);
                int2 mB = *reinterpret_cast<const int2*>(mbase + (size_t)(qrow + 8) * N_ + col);
                if (!mA.x) s[nt][0] = neg_inf();
                if (!mA.y) s[nt][1] = neg_inf();
                if (!mB.x) s[nt][2] = neg_inf();
                if (!mB.y) s[nt][3] = neg_inf();
            }
        }

        // online softmax in log2 domain (rows g, g+8)
        float mx0 = neg_inf(), mx1 = neg_inf();
        #pragma unroll
        for (int nt = 0; nt < 4; nt++) {
            mx0 = fmaxf(mx0, fmaxf(s[nt][0], s[nt][1]));
            mx1 = fmaxf(mx1, fmaxf(s[nt][2], s[nt][3]));
        }
        mx0 = fmaxf(mx0, __shfl_xor_sync(0xffffffffu, mx0, 1));
        mx0 = fmaxf(mx0, __shfl_xor_sync(0xffffffffu, mx0, 2));
        mx1 = fmaxf(mx1, __shfl_xor_sync(0xffffffffu, mx1, 1));
        mx1 = fmaxf(mx1, __shfl_xor_sync(0xffffffffu, mx1, 2));
        const float mn0 = fmaxf(mr0, mx0), mn1 = fmaxf(mr1, mx1);
        const float sc0 = fexp2(fmaxf(mr0 - mn0, -120.0f));  // fmax absorbs -inf/NaN
        const float sc1 = fexp2(fmaxf(mr1 - mn1, -120.0f));
        float sum0 = 0.0f, sum1 = 0.0f;
        #pragma unroll
        for (int nt = 0; nt < 4; nt++) {
            float p0 = f2tf(fexp2(fmaxf(s[nt][0] - mn0, -120.0f)));
            float p1 = f2tf(fexp2(fmaxf(s[nt][1] - mn0, -120.0f)));
            float p2 = f2tf(fexp2(fmaxf(s[nt][2] - mn1, -120.0f)));
            float p3 = f2tf(fexp2(fmaxf(s[nt][3] - mn1, -120.0f)));
            s[nt][0] = p0; s[nt][1] = p1; s[nt][2] = p2; s[nt][3] = p3;
            sum0 += p0 + p1; sum1 += p2 + p3;
        }
        sum0 += __shfl_xor_sync(0xffffffffu, sum0, 1);
        sum0 += __shfl_xor_sync(0xffffffffu, sum0, 2);
        sum1 += __shfl_xor_sync(0xffffffffu, sum1, 1);
        sum1 += __shfl_xor_sync(0xffffffffu, sum1, 2);
        lr0 = lr0 * sc0 + sum0; lr1 = lr1 * sc1 + sum1;
        mr0 = mn0; mr1 = mn1;

        // rescale O
        #pragma unroll
        for (int dt = 0; dt < 8; dt++) {
            o[dt][0] *= sc0; o[dt][1] *= sc0;
            o[dt][2] *= sc1; o[dt][3] *= sc1;
        }

        // O += P @ V : P a-frags built from c-frags via quad shfls.
        // P[g][c] lives in lane (g*4 + (c>>1)), slot (c&1) (+2 for row g+8).
        #pragma unroll
        for (int kp = 0; kp < 4; kp++) {
            const int srcA = (g << 2) | (tg >> 1);
            const int srcB = srcA + 2;
            const bool odd = (tg & 1);
            float v0 = __shfl_sync(0xffffffffu, s[kp][0], srcA);
            float v1 = __shfl_sync(0xffffffffu, s[kp][1], srcA);
            float v2 = __shfl_sync(0xffffffffu, s[kp][2], srcA);
            float v3 = __shfl_sync(0xffffffffu, s[kp][3], srcA);
            float w0 = __shfl_sync(0xffffffffu, s[kp][0], srcB);
            float w1 = __shfl_sync(0xffffffffu, s[kp][1], srcB);
            float w2 = __shfl_sync(0xffffffffu, s[kp][2], srcB);
            float w3 = __shfl_sync(0xffffffffu, s[kp][3], srcB);
            uint32_t a[4];
            a[0] = __float_as_uint(odd ? v1 : v0);   // P[g][kp*8+tg]
            a[1] = __float_as_uint(odd ? v3 : v2);   // P[g+8][kp*8+tg]
            a[2] = __float_as_uint(odd ? w1 : w0);   // P[g][kp*8+tg+4]
            a[3] = __float_as_uint(odd ? w3 : w2);   // P[g+8][kp*8+tg+4]
            #pragma unroll
            for (int dt = 0; dt < 8; dt++) {
                uint32_t bfr[2];
                const int vb = (kp * 8 + tg) * ST_ + dt * 8 + g;
                bfr[0] = __float_as_uint(Vc[vb]);
                bfr[1] = __float_as_uint(Vc[vb + 4 * ST_]);
                mma8(o[dt], a, bfr);
            }
        }
    }

    // Epilogue: normalize and recombine heads
    const float il0 = 1.0f / lr0, il1 = 1.0f / lr1;
    #pragma unroll
    for (int dt = 0; dt < 8; dt++) {
        const int dd = h * 64 + dt * 8 + 2 * tg;
        *reinterpret_cast<float2*>(&g_att[(size_t)(b * N_ + qrow) * E_ + dd]) =
            make_float2(o[dt][0] * il0, o[dt][1] * il0);
        *reinterpret_cast<float2*>(&g_att[(size_t)(b * N_ + qrow + 8) * E_ + dd]) =
            make_float2(o[dt][2] * il1, o[dt][3] * il1);
    }
}

// ---------------------------------------------------------------------------
extern "C" void kernel_launch(void* const* d_in, const int* in_sizes, int n_in,
                              void* d_out, int out_size)
{
    const float* Q    = (const float*)d_in[0];
    const float* K    = (const float*)d_in[1];
    const float* V    = (const float*)d_in[2];
    const int*   mask = (const int*)  d_in[3];
    const float* Wq   = (const float*)d_in[4];
    const float* Wk   = (const float*)d_in[5];
    const float* Wv   = (const float*)d_in[6];
    const float* Wo   = (const float*)d_in[7];
    const float* bo   = (const float*)d_in[8];
    const float* tau  = (const float*)d_in[9];
    float* out = (float*)d_out;

    const int gemm_smem = (128 * 36 * 2 + 64 * 36 * 2) * (int)sizeof(float);  // 55296

    cudaFuncSetAttribute(gemm_qkv, cudaFuncAttributeMaxDynamicSharedMemorySize, gemm_smem);
    cudaFuncSetAttribute(gemm_out, cudaFuncAttributeMaxDynamicSharedMemorySize, gemm_smem);

    mask_flags<<<dim3(NT_, NT_, B_), 256>>>(mask);

    gemm_qkv<<<dim3(E_ / 64, M_ / 128, 3), 256, gemm_smem>>>(Q, K, V, Wq, Wk, Wv, tau);

    // grid.x = heads (fastest) so the 8 heads sharing a mask tile are adjacent -> L2 reuse
    attn_tc<<<dim3(H_, N_ / 64, B_), 128>>>(mask);

    gemm_out<<<dim3(E_ / 64, M_ / 128), 256, gemm_smem>>>(Wo, bo, out);
}

// round 6
// speedup vs baseline: 2.4603x; 1.1062x over previous
#include <cuda_runtime.h>
#include <cstdint>
#include <cstddef>

// Problem constants
constexpr int B_ = 8;
constexpr int N_ = 2048;
constexpr int E_ = 512;
constexpr int H_ = 8;
constexpr int D_ = 64;
constexpr int M_ = B_ * N_;   // 16384 rows
constexpr int NT_ = N_ / 64;  // 32 64-row tiles (mask-flag granularity)
constexpr int KT_ = 32;       // attention kv-tile rows
constexpr int NKT_ = N_ / KT_;// 64 kv tiles
constexpr int ST_ = 68;       // attention smem row stride (floats)

// Scratch (device globals: allocation-free per harness rules)
__device__ float g_q[(size_t)B_ * H_ * N_ * D_];   // [b][h][n][d], pre-scaled by log2e/tau, tf32
__device__ float g_k[(size_t)B_ * H_ * N_ * D_];   // tf32-rounded
__device__ float g_v[(size_t)B_ * H_ * N_ * D_];   // tf32-rounded
__device__ float g_att[(size_t)M_ * E_];           // [b*n][h*d] recombined heads
__device__ int   g_mflag[B_ * NT_ * NT_];          // 1 = 64x64 tile all-nonzero
__device__ float g_wh[4][(size_t)E_ * E_];         // tf32 hi parts of Wq,Wk,Wv,Wo
__device__ float g_wl[4][(size_t)E_ * E_];         // tf32 lo parts

__device__ __forceinline__ float neg_inf() { return __int_as_float(0xff800000); }

__device__ __forceinline__ float f2tf(float x) {
    uint32_t r;
    asm("cvt.rna.tf32.f32 %0, %1;" : "=r"(r) : "f"(x));
    return __uint_as_float(r);
}

__device__ __forceinline__ float fexp2(float x) {
    float y;
    asm("ex2.approx.ftz.f32 %0, %1;" : "=f"(y) : "f"(x));
    return y;
}

// m16n8k8 tf32 mma: c += a * b
__device__ __forceinline__ void mma8(float* c, const uint32_t* a, const uint32_t* b) {
    asm volatile(
        "mma.sync.aligned.m16n8k8.row.col.f32.tf32.tf32.f32 "
        "{%0,%1,%2,%3}, {%4,%5,%6,%7}, {%8,%9}, {%0,%1,%2,%3};\n"
        : "+f"(c[0]), "+f"(c[1]), "+f"(c[2]), "+f"(c[3])
        : "r"(a[0]), "r"(a[1]), "r"(a[2]), "r"(a[3]), "r"(b[0]), "r"(b[1]));
}

// cp.async helpers
__device__ __forceinline__ void cp16(const float* smem_dst, const float* gmem_src) {
    uint32_t s = (uint32_t)__cvta_generic_to_shared(smem_dst);
    asm volatile("cp.async.ca.shared.global [%0], [%1], 16;" :: "r"(s), "l"(gmem_src));
}
__device__ __forceinline__ void cp_commit() { asm volatile("cp.async.commit_group;"); }
template<int N>
__device__ __forceinline__ void cp_wait() { asm volatile("cp.async.wait_group %0;" :: "n"(N) : "memory"); }

// ---------------------------------------------------------------------------
// One-time weight split: W -> (hi, lo) tf32 pair. blockIdx.y selects matrix.
// ---------------------------------------------------------------------------
__global__ __launch_bounds__(256)
void split_w(const float* __restrict__ Wq, const float* __restrict__ Wk,
             const float* __restrict__ Wv, const float* __restrict__ Wo)
{
    const int m = blockIdx.y;
    const float* W = (m == 0) ? Wq : (m == 1) ? Wk : (m == 2) ? Wv : Wo;
    const size_t i4 = ((size_t)blockIdx.x * 256 + threadIdx.x) * 4;
    float4 v = *reinterpret_cast<const float4*>(W + i4);
    float4 h = make_float4(f2tf(v.x), f2tf(v.y), f2tf(v.z), f2tf(v.w));
    *reinterpret_cast<float4*>(&g_wh[m][i4]) = h;
    *reinterpret_cast<float4*>(&g_wl[m][i4]) =
        make_float4(f2tf(v.x - h.x), f2tf(v.y - h.y), f2tf(v.z - h.z), f2tf(v.w - h.w));
}

// ---------------------------------------------------------------------------
// Mask preprocessing: one flag per (b, 64-row q tile, 64-col kv tile).
// ---------------------------------------------------------------------------
__global__ __launch_bounds__(256)
void mask_flags(const int* __restrict__ mask)
{
    const int kvt = blockIdx.x, qt = blockIdx.y, b = blockIdx.z;
    const int tid = threadIdx.x;
    const int r = tid >> 2, c0 = (tid & 3) * 16;
    const int* base = mask + (size_t)b * N_ * N_ + (size_t)(qt * 64 + r) * N_ + kvt * 64 + c0;
    bool ok = true;
    #pragma unroll
    for (int i = 0; i < 4; i++) {
        int4 m = *reinterpret_cast<const int4*>(base + i * 4);
        ok &= (m.x != 0) & (m.y != 0) & (m.z != 0) & (m.w != 0);
    }
    int all = __syncthreads_and((int)ok);
    if (tid == 0) g_mflag[(b * NT_ + qt) * NT_ + kvt] = all;
}

// ---------------------------------------------------------------------------
// GEMM core v2: Y = tf32(X) @ (Wh + Wl)^T, 2 mma passes, cp.async double
// buffer. Block 128x64, BK=32, 256 thr = 8 warps (4m x 2n), warp 32x32.
// Smem/buffer: X raw fp32 [128][36], Wh [64][36], Wl [64][36]; x2 buffers.
// widx selects the pre-split weight matrix.
// ---------------------------------------------------------------------------
constexpr int GX_ = 128 * 36;          // X tile floats
constexpr int GW_ = 64 * 36;           // W tile floats
constexpr int GBUF_ = GX_ + 2 * GW_;   // one buffer: 9216 floats
constexpr int GKT_ = E_ / 32;          // 16 k tiles

__device__ __forceinline__ void gemm_prefetch(const float* __restrict__ X, int widx,
                                              float* buf, int m0, int n0, int kt)
{
    const int tid = threadIdx.x;
    const float* Wh = g_wh[widx];
    const float* Wl = g_wl[widx];
    #pragma unroll
    for (int i = 0; i < 4; i++) {
        int idx = tid + i * 256;              // 0..1023
        int r = idx >> 3, c = (idx & 7) * 4;
        cp16(&buf[r * 36 + c], X + (size_t)(m0 + r) * E_ + kt * 32 + c);
    }
    #pragma unroll
    for (int i = 0; i < 2; i++) {
        int idx = tid + i * 256;              // 0..511
        int r = idx >> 3, c = (idx & 7) * 4;
        cp16(&buf[GX_ + r * 36 + c],       Wh + (size_t)(n0 + r) * E_ + kt * 32 + c);
        cp16(&buf[GX_ + GW_ + r * 36 + c], Wl + (size_t)(n0 + r) * E_ + kt * 32 + c);
    }
    cp_commit();
}

__device__ __forceinline__ void gemm_core2(const float* __restrict__ X, int widx,
                                           float* sm, int m0, int n0,
                                           float acc[2][4][4])
{
    const int tid = threadIdx.x;
    const int warp = tid >> 5, lane = tid & 31;
    const int g = lane >> 2, tg = lane & 3;
    const int wm = warp >> 1, wn = warp & 1;

    gemm_prefetch(X, widx, sm, m0, n0, 0);

    for (int kt = 0; kt < GKT_; kt++) {
        if (kt + 1 < GKT_) {
            gemm_prefetch(X, widx, sm + ((kt + 1) & 1) * GBUF_, m0, n0, kt + 1);
            cp_wait<1>();
        } else {
            cp_wait<0>();
        }
        __syncthreads();
        const float* Xs = sm + (kt & 1) * GBUF_;
        const float* Whs = Xs + GX_;
        const float* Wls = Whs + GW_;

        #pragma unroll
        for (int ks = 0; ks < 4; ks++) {
            const int k0 = ks * 8;
            uint32_t Ah[2][4], Bh[4][2], Bl[4][2];
            #pragma unroll
            for (int mt = 0; mt < 2; mt++) {
                const int rb = (wm * 32 + mt * 16) * 36 + k0;
                Ah[mt][0] = __float_as_uint(f2tf(Xs[rb + g * 36 + tg]));
                Ah[mt][1] = __float_as_uint(f2tf(Xs[rb + (g + 8) * 36 + tg]));
                Ah[mt][2] = __float_as_uint(f2tf(Xs[rb + g * 36 + tg + 4]));
                Ah[mt][3] = __float_as_uint(f2tf(Xs[rb + (g + 8) * 36 + tg + 4]));
            }
            #pragma unroll
            for (int nt = 0; nt < 4; nt++) {
                const int rb = (wn * 32 + nt * 8 + g) * 36 + k0;
                Bh[nt][0] = __float_as_uint(Whs[rb + tg]);
                Bh[nt][1] = __float_as_uint(Whs[rb + tg + 4]);
                Bl[nt][0] = __float_as_uint(Wls[rb + tg]);
                Bl[nt][1] = __float_as_uint(Wls[rb + tg + 4]);
            }
            #pragma unroll
            for (int mt = 0; mt < 2; mt++)
                #pragma unroll
                for (int nt = 0; nt < 4; nt++) {
                    mma8(acc[mt][nt], Ah[mt], Bh[nt]);
                    mma8(acc[mt][nt], Ah[mt], Bl[nt]);
                }
        }
        __syncthreads();   // all warps done before next prefetch overwrites this buffer
    }
}

// QKV projections fused; outputs pre-formatted for attention:
//  z=0 (Q): scaled by log2e/tau, tf32-rounded.  z=1 (K), z=2 (V): tf32-rounded.
__global__ __launch_bounds__(256)
void gemm_qkv(const float* __restrict__ Qi, const float* __restrict__ Ki,
              const float* __restrict__ Vi, const float* __restrict__ taup)
{
    extern __shared__ float sm[];
    const int z = blockIdx.z;
    const float* X = (z == 0) ? Qi : (z == 1) ? Ki : Vi;
    float* Y = (z == 0) ? g_q : (z == 1) ? g_k : g_v;
    const float scl = (z == 0) ? (1.4426950408889634f / __ldg(taup)) : 1.0f;

    const int m0 = blockIdx.y * 128, n0 = blockIdx.x * 64;
    float acc[2][4][4] = {};
    gemm_core2(X, z, sm, m0, n0, acc);

    const int tid = threadIdx.x;
    const int warp = tid >> 5, lane = tid & 31;
    const int g = lane >> 2, tg = lane & 3;
    const int wm = warp >> 1, wn = warp & 1;
    const int h = blockIdx.x;              // BN=64 == head dim
    #pragma unroll
    for (int mt = 0; mt < 2; mt++) {
        #pragma unroll
        for (int nt = 0; nt < 4; nt++) {
            const int dd = wn * 32 + nt * 8 + 2 * tg;
            int m = m0 + wm * 32 + mt * 16 + g;
            int b = m >> 11, n = m & (N_ - 1);
            *reinterpret_cast<float2*>(&Y[((size_t)((b * H_ + h) * N_ + n)) * D_ + dd]) =
                make_float2(f2tf(acc[mt][nt][0] * scl), f2tf(acc[mt][nt][1] * scl));
            m += 8; b = m >> 11; n = m & (N_ - 1);
            *reinterpret_cast<float2*>(&Y[((size_t)((b * H_ + h) * N_ + n)) * D_ + dd]) =
                make_float2(f2tf(acc[mt][nt][2] * scl), f2tf(acc[mt][nt][3] * scl));
        }
    }
}

// Output projection: g_att @ Wo^T + bo -> out
__global__ __launch_bounds__(256)
void gemm_out(const float* __restrict__ bias, float* __restrict__ Yext)
{
    extern __shared__ float sm[];
    const int m0 = blockIdx.y * 128, n0 = blockIdx.x * 64;
    float acc[2][4][4] = {};
    gemm_core2(g_att, 3, sm, m0, n0, acc);

    const int tid = threadIdx.x;
    const int warp = tid >> 5, lane = tid & 31;
    const int g = lane >> 2, tg = lane & 3;
    const int wm = warp >> 1, wn = warp & 1;
    #pragma unroll
    for (int mt = 0; mt < 2; mt++) {
        #pragma unroll
        for (int nt = 0; nt < 4; nt++) {
            const int o = n0 + wn * 32 + nt * 8 + 2 * tg;
            float2 bb = *reinterpret_cast<const float2*>(bias + o);
            const int m = m0 + wm * 32 + mt * 16 + g;
            *reinterpret_cast<float2*>(&Yext[(size_t)m * E_ + o]) =
                make_float2(acc[mt][nt][0] + bb.x, acc[mt][nt][1] + bb.y);
            *reinterpret_cast<float2*>(&Yext[(size_t)(m + 8) * E_ + o]) =
                make_float2(acc[mt][nt][2] + bb.x, acc[mt][nt][3] + bb.y);
        }
    }
}

// ---------------------------------------------------------------------------
// Flash attention v3 (unchanged from R5): tf32 mma, cp.async double-buffered
// kv tiles of 32 rows, P via quad shfls, softmax in log2 domain.
// ---------------------------------------------------------------------------
__global__ __launch_bounds__(128, 5)
void attn_tc(const int* __restrict__ mask)
{
    __shared__ float sm[4 * KT_ * ST_];

    const int h = blockIdx.x, qt = blockIdx.y, b = blockIdx.z;
    const int tid = threadIdx.x;
    const int warp = tid >> 5, lane = tid & 31;
    const int g = lane >> 2, tg = lane & 3;
    const int q0 = qt * 64;

    const size_t bh = (size_t)(b * H_ + h) * N_ * D_;
    const float* qbase = g_q + bh;
    const float* kbase = g_k + bh;
    const float* vbase = g_v + bh;
    const int* mbase = mask + (size_t)b * N_ * N_;
    const int* fbase = g_mflag + (b * NT_ + qt) * NT_;

    // Stage Q (64x64, already scaled+tf32) through the buffer region
    {
        #pragma unroll
        for (int i = 0; i < 8; i++) {
            int idx = tid + i * 128;
            int r = idx >> 4, c = (idx & 15) * 4;
            cp16(&sm[r * ST_ + c], qbase + (size_t)(q0 + r) * D_ + c);
        }
        cp_commit(); cp_wait<0>();
        __syncthreads();
    }

    uint32_t q_a[8][4];
    #pragma unroll
    for (int kp = 0; kp < 8; kp++) {
        const int qb = (warp * 16) * ST_ + kp * 8;
        q_a[kp][0] = __float_as_uint(sm[qb + g * ST_ + tg]);
        q_a[kp][1] = __float_as_uint(sm[qb + (g + 8) * ST_ + tg]);
        q_a[kp][2] = __float_as_uint(sm[qb + g * ST_ + tg + 4]);
        q_a[kp][3] = __float_as_uint(sm[qb + (g + 8) * ST_ + tg + 4]);
    }
    __syncthreads();

    // Prefetch kv tile 0 into buf 0
    {
        #pragma unroll
        for (int i = 0; i < 4; i++) {
            int idx = tid + i * 128;
            int r = idx >> 4, c = (idx & 15) * 4;
            cp16(&sm[r * ST_ + c],        kbase + (size_t)r * D_ + c);
            cp16(&sm[2176 + r * ST_ + c], vbase + (size_t)r * D_ + c);
        }
        cp_commit();
    }

    float o[8][4] = {};
    float mr0 = neg_inf(), mr1 = neg_inf();
    float lr0 = 0.0f, lr1 = 0.0f;
    const int qrow = q0 + warp * 16 + g;

    for (int t = 0; t < NKT_; t++) {
        cp_wait<0>();
        __syncthreads();

        if (t + 1 < NKT_) {
            const float* kb2 = kbase + (size_t)(t + 1) * KT_ * D_;
            const float* vb2 = vbase + (size_t)(t + 1) * KT_ * D_;
            float* dst = sm + ((t + 1) & 1) * 4352;
            #pragma unroll
            for (int i = 0; i < 4; i++) {
                int idx = tid + i * 128;
                int r = idx >> 4, c = (idx & 15) * 4;
                cp16(&dst[r * ST_ + c],        kb2 + (size_t)r * D_ + c);
                cp16(&dst[2176 + r * ST_ + c], vb2 + (size_t)r * D_ + c);
            }
            cp_commit();
        }

        const float* Kc = sm + (t & 1) * 4352;
        const float* Vc = Kc + 2176;
        const int kv0 = t * KT_;
        const int clean = __ldg(fbase + (t >> 1));

        float s[4][4] = {};
        #pragma unroll
        for (int kp = 0; kp < 8; kp++) {
            #pragma unroll
            for (int nt = 0; nt < 4; nt++) {
                uint32_t bfr[2];
                const int kb = (nt * 8 + g) * ST_ + kp * 8 + tg;
                bfr[0] = __float_as_uint(Kc[kb]);
                bfr[1] = __float_as_uint(Kc[kb + 4]);
                mma8(s[nt], q_a[kp], bfr);
            }
        }

        if (!clean) {
            #pragma unroll
            for (int nt = 0; nt < 4; nt++) {
                const int col = kv0 + nt * 8 + 2 * tg;
                int2 mA = *reinterpret_cast<const int2*>(mbase + (size_t)qrow * N_ + col);
                int2 mB = *reinterpret_cast<const int2*>(mbase + (size_t)(qrow + 8) * N_ + col);
                if (!mA.x) s[nt][0] = neg_inf();
                if (!mA.y) s[nt][1] = neg_inf();
                if (!mB.x) s[nt][2] = neg_inf();
                if (!mB.y) s[nt][3] = neg_inf();
            }
        }

        float mx0 = neg_inf(), mx1 = neg_inf();
        #pragma unroll
        for (int nt = 0; nt < 4; nt++) {
            mx0 = fmaxf(mx0, fmaxf(s[nt][0], s[nt][1]));
            mx1 = fmaxf(mx1, fmaxf(s[nt][2], s[nt][3]));
        }
        mx0 = fmaxf(mx0, __shfl_xor_sync(0xffffffffu, mx0, 1));
        mx0 = fmaxf(mx0, __shfl_xor_sync(0xffffffffu, mx0, 2));
        mx1 = fmaxf(mx1, __shfl_xor_sync(0xffffffffu, mx1, 1));
        mx1 = fmaxf(mx1, __shfl_xor_sync(0xffffffffu, mx1, 2));
        const float mn0 = fmaxf(mr0, mx0), mn1 = fmaxf(mr1, mx1);
        const float sc0 = fexp2(fmaxf(mr0 - mn0, -120.0f));
        const float sc1 = fexp2(fmaxf(mr1 - mn1, -120.0f));
        float sum0 = 0.0f, sum1 = 0.0f;
        #pragma unroll
        for (int nt = 0; nt < 4; nt++) {
            float p0 = f2tf(fexp2(fmaxf(s[nt][0] - mn0, -120.0f)));
            float p1 = f2tf(fexp2(fmaxf(s[nt][1] - mn0, -120.0f)));
            float p2 = f2tf(fexp2(fmaxf(s[nt][2] - mn1, -120.0f)));
            float p3 = f2tf(fexp2(fmaxf(s[nt][3] - mn1, -120.0f)));
            s[nt][0] = p0; s[nt][1] = p1; s[nt][2] = p2; s[nt][3] = p3;
            sum0 += p0 + p1; sum1 += p2 + p3;
        }
        sum0 += __shfl_xor_sync(0xffffffffu, sum0, 1);
        sum0 += __shfl_xor_sync(0xffffffffu, sum0, 2);
        sum1 += __shfl_xor_sync(0xffffffffu, sum1, 1);
        sum1 += __shfl_xor_sync(0xffffffffu, sum1, 2);
        lr0 = lr0 * sc0 + sum0; lr1 = lr1 * sc1 + sum1;
        mr0 = mn0; mr1 = mn1;

        #pragma unroll
        for (int dt = 0; dt < 8; dt++) {
            o[dt][0] *= sc0; o[dt][1] *= sc0;
            o[dt][2] *= sc1; o[dt][3] *= sc1;
        }

        // O += P @ V : P a-frags via quad shfls
        #pragma unroll
        for (int kp = 0; kp < 4; kp++) {
            const int srcA = (g << 2) | (tg >> 1);
            const int srcB = srcA + 2;
            const bool odd = (tg & 1);
            float v0 = __shfl_sync(0xffffffffu, s[kp][0], srcA);
            float v1 = __shfl_sync(0xffffffffu, s[kp][1], srcA);
            float v2 = __shfl_sync(0xffffffffu, s[kp][2], srcA);
            float v3 = __shfl_sync(0xffffffffu, s[kp][3], srcA);
            float w0 = __shfl_sync(0xffffffffu, s[kp][0], srcB);
            float w1 = __shfl_sync(0xffffffffu, s[kp][1], srcB);
            float w2 = __shfl_sync(0xffffffffu, s[kp][2], srcB);
            float w3 = __shfl_sync(0xffffffffu, s[kp][3], srcB);
            uint32_t a[4];
            a[0] = __float_as_uint(odd ? v1 : v0);
            a[1] = __float_as_uint(odd ? v3 : v2);
            a[2] = __float_as_uint(odd ? w1 : w0);
            a[3] = __float_as_uint(odd ? w3 : w2);
            #pragma unroll
            for (int dt = 0; dt < 8; dt++) {
                uint32_t bfr[2];
                const int vb = (kp * 8 + tg) * ST_ + dt * 8 + g;
                bfr[0] = __float_as_uint(Vc[vb]);
                bfr[1] = __float_as_uint(Vc[vb + 4 * ST_]);
                mma8(o[dt], a, bfr);
            }
        }
    }

    const float il0 = 1.0f / lr0, il1 = 1.0f / lr1;
    #pragma unroll
    for (int dt = 0; dt < 8; dt++) {
        const int dd = h * 64 + dt * 8 + 2 * tg;
        *reinterpret_cast<float2*>(&g_att[(size_t)(b * N_ + qrow) * E_ + dd]) =
            make_float2(o[dt][0] * il0, o[dt][1] * il0);
        *reinterpret_cast<float2*>(&g_att[(size_t)(b * N_ + qrow + 8) * E_ + dd]) =
            make_float2(o[dt][2] * il1, o[dt][3] * il1);
    }
}

// ---------------------------------------------------------------------------
extern "C" void kernel_launch(void* const* d_in, const int* in_sizes, int n_in,
                              void* d_out, int out_size)
{
    const float* Q    = (const float*)d_in[0];
    const float* K    = (const float*)d_in[1];
    const float* V    = (const float*)d_in[2];
    const int*   mask = (const int*)  d_in[3];
    const float* Wq   = (const float*)d_in[4];
    const float* Wk   = (const float*)d_in[5];
    const float* Wv   = (const float*)d_in[6];
    const float* Wo   = (const float*)d_in[7];
    const float* bo   = (const float*)d_in[8];
    const float* tau  = (const float*)d_in[9];
    float* out = (float*)d_out;

    const int gemm_smem = 2 * GBUF_ * (int)sizeof(float);  // 73728

    cudaFuncSetAttribute(gemm_qkv, cudaFuncAttributeMaxDynamicSharedMemorySize, gemm_smem);
    cudaFuncSetAttribute(gemm_out, cudaFuncAttributeMaxDynamicSharedMemorySize, gemm_smem);

    split_w<<<dim3(E_ * E_ / (256 * 4), 4), 256>>>(Wq, Wk, Wv, Wo);
    mask_flags<<<dim3(NT_, NT_, B_), 256>>>(mask);

    gemm_qkv<<<dim3(E_ / 64, M_ / 128, 3), 256, gemm_smem>>>(Q, K, V, tau);

    // grid.x = heads (fastest) so the 8 heads sharing a mask tile are adjacent -> L2 reuse
    attn_tc<<<dim3(H_, N_ / 64, B_), 128>>>(mask);

    gemm_out<<<dim3(E_ / 64, M_ / 128), 256, gemm_smem>>>(bo, out);
}

// round 8
// speedup vs baseline: 3.0917x; 1.2566x over previous
#include <cuda_runtime.h>
#include <cstdint>
#include <cstddef>

// Problem constants
constexpr int B_ = 8;
constexpr int N_ = 2048;
constexpr int E_ = 512;
constexpr int H_ = 8;
constexpr int D_ = 64;
constexpr int M_ = B_ * N_;   // 16384 rows
constexpr int NT_ = N_ / 64;  // 32 64-row tiles (mask-flag granularity)
constexpr int KT_ = 32;       // attention kv-tile rows
constexpr int NKT_ = N_ / KT_;// 64 kv tiles
constexpr int ST_ = 68;       // attention smem row stride (floats)

// Scratch (device globals: allocation-free per harness rules)
__device__ float g_q[(size_t)B_ * H_ * N_ * D_];   // [b][h][n][d], pre-scaled by log2e/tau, tf32
__device__ float g_k[(size_t)B_ * H_ * N_ * D_];   // tf32-rounded
__device__ float g_v[(size_t)B_ * H_ * N_ * D_];   // tf32-rounded
__device__ float g_att[(size_t)M_ * E_];           // [b*n][h*d] recombined heads
__device__ int   g_mflag[B_ * NT_ * NT_];          // 1 = 64x64 tile all-nonzero
__device__ float g_wh[4][(size_t)E_ * E_];         // tf32 hi parts of Wq,Wk,Wv,Wo
__device__ float g_wl[4][(size_t)E_ * E_];         // tf32 lo parts

__device__ __forceinline__ float neg_inf() { return __int_as_float(0xff800000); }

__device__ __forceinline__ float f2tf(float x) {
    uint32_t r;
    asm("cvt.rna.tf32.f32 %0, %1;" : "=r"(r) : "f"(x));
    return __uint_as_float(r);
}

__device__ __forceinline__ float fexp2(float x) {
    float y;
    asm("ex2.approx.ftz.f32 %0, %1;" : "=f"(y) : "f"(x));
    return y;
}

// m16n8k8 tf32 mma: c += a * b
__device__ __forceinline__ void mma8(float* c, const uint32_t* a, const uint32_t* b) {
    asm volatile(
        "mma.sync.aligned.m16n8k8.row.col.f32.tf32.tf32.f32 "
        "{%0,%1,%2,%3}, {%4,%5,%6,%7}, {%8,%9}, {%0,%1,%2,%3};\n"
        : "+f"(c[0]), "+f"(c[1]), "+f"(c[2]), "+f"(c[3])
        : "r"(a[0]), "r"(a[1]), "r"(a[2]), "r"(a[3]), "r"(b[0]), "r"(b[1]));
}

// cp.async helpers
__device__ __forceinline__ void cp16(const float* smem_dst, const float* gmem_src) {
    uint32_t s = (uint32_t)__cvta_generic_to_shared(smem_dst);
    asm volatile("cp.async.ca.shared.global [%0], [%1], 16;" :: "r"(s), "l"(gmem_src));
}
__device__ __forceinline__ void cp_commit() { asm volatile("cp.async.commit_group;"); }
template<int N>
__device__ __forceinline__ void cp_wait() { asm volatile("cp.async.wait_group %0;" :: "n"(N) : "memory"); }

// ---------------------------------------------------------------------------
// One-time weight split: W -> (hi, lo) tf32 pair. blockIdx.y selects matrix.
// ---------------------------------------------------------------------------
__global__ __launch_bounds__(256)
void split_w(const float* __restrict__ Wq, const float* __restrict__ Wk,
             const float* __restrict__ Wv, const float* __restrict__ Wo)
{
    const int m = blockIdx.y;
    const float* W = (m == 0) ? Wq : (m == 1) ? Wk : (m == 2) ? Wv : Wo;
    const size_t i4 = ((size_t)blockIdx.x * 256 + threadIdx.x) * 4;
    float4 v = *reinterpret_cast<const float4*>(W + i4);
    float4 h = make_float4(f2tf(v.x), f2tf(v.y), f2tf(v.z), f2tf(v.w));
    *reinterpret_cast<float4*>(&g_wh[m][i4]) = h;
    *reinterpret_cast<float4*>(&g_wl[m][i4]) =
        make_float4(f2tf(v.x - h.x), f2tf(v.y - h.y), f2tf(v.z - h.z), f2tf(v.w - h.w));
}

// ---------------------------------------------------------------------------
// Mask preprocessing: one flag per (b, 64-row q tile, 64-col kv tile).
// ---------------------------------------------------------------------------
__global__ __launch_bounds__(256)
void mask_flags(const int* __restrict__ mask)
{
    const int kvt = blockIdx.x, qt = blockIdx.y, b = blockIdx.z;
    const int tid = threadIdx.x;
    const int r = tid >> 2, c0 = (tid & 3) * 16;
    const int* base = mask + (size_t)b * N_ * N_ + (size_t)(qt * 64 + r) * N_ + kvt * 64 + c0;
    bool ok = true;
    #pragma unroll
    for (int i = 0; i < 4; i++) {
        int4 m = *reinterpret_cast<const int4*>(base + i * 4);
        ok &= (m.x != 0) & (m.y != 0) & (m.z != 0) & (m.w != 0);
    }
    int all = __syncthreads_and((int)ok);
    if (tid == 0) g_mflag[(b * NT_ + qt) * NT_ + kvt] = all;
}

// ---------------------------------------------------------------------------
// GEMM core (R6): Y = tf32(X) @ (Wh + Wl)^T, 2 mma passes, cp.async double
// buffer. Block 128x64, BK=32, 256 thr = 8 warps (4m x 2n), warp 32x32.
// ---------------------------------------------------------------------------
constexpr int GX_ = 128 * 36;
constexpr int GW_ = 64 * 36;
constexpr int GBUF_ = GX_ + 2 * GW_;
constexpr int GKT_ = E_ / 32;

__device__ __forceinline__ void gemm_prefetch(const float* __restrict__ X, int widx,
                                              float* buf, int m0, int n0, int kt)
{
    const int tid = threadIdx.x;
    const float* Wh = g_wh[widx];
    const float* Wl = g_wl[widx];
    #pragma unroll
    for (int i = 0; i < 4; i++) {
        int idx = tid + i * 256;
        int r = idx >> 3, c = (idx & 7) * 4;
        cp16(&buf[r * 36 + c], X + (size_t)(m0 + r) * E_ + kt * 32 + c);
    }
    #pragma unroll
    for (int i = 0; i < 2; i++) {
        int idx = tid + i * 256;
        int r = idx >> 3, c = (idx & 7) * 4;
        cp16(&buf[GX_ + r * 36 + c],       Wh + (size_t)(n0 + r) * E_ + kt * 32 + c);
        cp16(&buf[GX_ + GW_ + r * 36 + c], Wl + (size_t)(n0 + r) * E_ + kt * 32 + c);
    }
    cp_commit();
}

__device__ __forceinline__ void gemm_core2(const float* __restrict__ X, int widx,
                                           float* sm, int m0, int n0,
                                           float acc[2][4][4])
{
    const int tid = threadIdx.x;
    const int warp = tid >> 5, lane = tid & 31;
    const int g = lane >> 2, tg = lane & 3;
    const int wm = warp >> 1, wn = warp & 1;

    gemm_prefetch(X, widx, sm, m0, n0, 0);

    for (int kt = 0; kt < GKT_; kt++) {
        if (kt + 1 < GKT_) {
            gemm_prefetch(X, widx, sm + ((kt + 1) & 1) * GBUF_, m0, n0, kt + 1);
            cp_wait<1>();
        } else {
            cp_wait<0>();
        }
        __syncthreads();
        const float* Xs = sm + (kt & 1) * GBUF_;
        const float* Whs = Xs + GX_;
        const float* Wls = Whs + GW_;

        #pragma unroll
        for (int ks = 0; ks < 4; ks++) {
            const int k0 = ks * 8;
            uint32_t Ah[2][4], Bh[4][2], Bl[4][2];
            #pragma unroll
            for (int mt = 0; mt < 2; mt++) {
                const int rb = (wm * 32 + mt * 16) * 36 + k0;
                Ah[mt][0] = __float_as_uint(f2tf(Xs[rb + g * 36 + tg]));
                Ah[mt][1] = __float_as_uint(f2tf(Xs[rb + (g + 8) * 36 + tg]));
                Ah[mt][2] = __float_as_uint(f2tf(Xs[rb + g * 36 + tg + 4]));
                Ah[mt][3] = __float_as_uint(f2tf(Xs[rb + (g + 8) * 36 + tg + 4]));
            }
            #pragma unroll
            for (int nt = 0; nt < 4; nt++) {
                const int rb = (wn * 32 + nt * 8 + g) * 36 + k0;
                Bh[nt][0] = __float_as_uint(Whs[rb + tg]);
                Bh[nt][1] = __float_as_uint(Whs[rb + tg + 4]);
                Bl[nt][0] = __float_as_uint(Wls[rb + tg]);
                Bl[nt][1] = __float_as_uint(Wls[rb + tg + 4]);
            }
            #pragma unroll
            for (int mt = 0; mt < 2; mt++)
                #pragma unroll
                for (int nt = 0; nt < 4; nt++) {
                    mma8(acc[mt][nt], Ah[mt], Bh[nt]);
                    mma8(acc[mt][nt], Ah[mt], Bl[nt]);
                }
        }
        __syncthreads();
    }
}

// QKV projections fused; outputs pre-formatted for attention.
__global__ __launch_bounds__(256)
void gemm_qkv(const float* __restrict__ Qi, const float* __restrict__ Ki,
              const float* __restrict__ Vi, const float* __restrict__ taup)
{
    extern __shared__ float sm[];
    const int z = blockIdx.z;
    const float* X = (z == 0) ? Qi : (z == 1) ? Ki : Vi;
    float* Y = (z == 0) ? g_q : (z == 1) ? g_k : g_v;
    const float scl = (z == 0) ? (1.4426950408889634f / __ldg(taup)) : 1.0f;

    const int m0 = blockIdx.y * 128, n0 = blockIdx.x * 64;
    float acc[2][4][4] = {};
    gemm_core2(X, z, sm, m0, n0, acc);

    const int tid = threadIdx.x;
    const int warp = tid >> 5, lane = tid & 31;
    const int g = lane >> 2, tg = lane & 3;
    const int wm = warp >> 1, wn = warp & 1;
    const int h = blockIdx.x;              // BN=64 == head dim
    #pragma unroll
    for (int mt = 0; mt < 2; mt++) {
        #pragma unroll
        for (int nt = 0; nt < 4; nt++) {
            const int dd = wn * 32 + nt * 8 + 2 * tg;
            int m = m0 + wm * 32 + mt * 16 + g;
            int b = m >> 11, n = m & (N_ - 1);
            *reinterpret_cast<float2*>(&Y[((size_t)((b * H_ + h) * N_ + n)) * D_ + dd]) =
                make_float2(f2tf(acc[mt][nt][0] * scl), f2tf(acc[mt][nt][1] * scl));
            m += 8; b = m >> 11; n = m & (N_ - 1);
            *reinterpret_cast<float2*>(&Y[((size_t)((b * H_ + h) * N_ + n)) * D_ + dd]) =
                make_float2(f2tf(acc[mt][nt][2] * scl), f2tf(acc[mt][nt][3] * scl));
        }
    }
}

// Output projection: g_att @ Wo^T + bo -> out
__global__ __launch_bounds__(256)
void gemm_out(const float* __restrict__ bias, float* __restrict__ Yext)
{
    extern __shared__ float sm[];
    const int m0 = blockIdx.y * 128, n0 = blockIdx.x * 64;
    float acc[2][4][4] = {};
    gemm_core2(g_att, 3, sm, m0, n0, acc);

    const int tid = threadIdx.x;
    const int warp = tid >> 5, lane = tid & 31;
    const int g = lane >> 2, tg = lane & 3;
    const int wm = warp >> 1, wn = warp & 1;
    #pragma unroll
    for (int mt = 0; mt < 2; mt++) {
        #pragma unroll
        for (int nt = 0; nt < 4; nt++) {
            const int o = n0 + wn * 32 + nt * 8 + 2 * tg;
            float2 bb = *reinterpret_cast<const float2*>(bias + o);
            const int m = m0 + wm * 32 + mt * 16 + g;
            *reinterpret_cast<float2*>(&Yext[(size_t)m * E_ + o]) =
                make_float2(acc[mt][nt][0] + bb.x, acc[mt][nt][1] + bb.y);
            *reinterpret_cast<float2*>(&Yext[(size_t)(m + 8) * E_ + o]) =
                make_float2(acc[mt][nt][2] + bb.x, acc[mt][nt][3] + bb.y);
        }
    }
}

// ---------------------------------------------------------------------------
// Flash attention v4: 128 q-rows per block, 4 warps x 32 rows (two 16-row mma
// groups u=0,1 per warp). Each K/V fragment is loaded from smem ONCE and feeds
// both groups' mma -> smem crossbar traffic per unit work is HALVED vs v3.
// cp.async double-buffered kv tiles of 32 rows; P via quad shfls; log2 softmax.
// Smem 34816B (Q staging reuses the KV buffers). ~180 regs -> 2 blocks/SM.
// ---------------------------------------------------------------------------
__global__ __launch_bounds__(128, 2)
void attn_tc(const int* __restrict__ mask)
{
    __shared__ float sm[4 * KT_ * ST_];   // 34816 B

    const int h = blockIdx.x, qt = blockIdx.y, b = blockIdx.z;
    const int tid = threadIdx.x;
    const int warp = tid >> 5, lane = tid & 31;
    const int g = lane >> 2, tg = lane & 3;
    const int q0 = qt * 128;

    const size_t bh = (size_t)(b * H_ + h) * N_ * D_;
    const float* qbase = g_q + bh;
    const float* kbase = g_k + bh;
    const float* vbase = g_v + bh;
    const int* mbase = mask + (size_t)b * N_ * N_;
    const int* fb0 = g_mflag + (b * NT_ + 2 * qt) * NT_;
    const int* fb1 = fb0 + NT_;

    // Stage Q (128x64, already scaled+tf32) through the buffer region
    {
        #pragma unroll
        for (int i = 0; i < 16; i++) {
            int idx = tid + i * 128;             // 0..2047
            int r = idx >> 4, c = (idx & 15) * 4;
            cp16(&sm[r * ST_ + c], qbase + (size_t)(q0 + r) * D_ + c);
        }
        cp_commit(); cp_wait<0>();
        __syncthreads();
    }

    // Hoist Q a-frags for both 16-row groups
    uint32_t q_a[2][8][4];
    #pragma unroll
    for (int u = 0; u < 2; u++) {
        #pragma unroll
        for (int kp = 0; kp < 8; kp++) {
            const int qb = (warp * 32 + u * 16) * ST_ + kp * 8;
            q_a[u][kp][0] = __float_as_uint(sm[qb + g * ST_ + tg]);
            q_a[u][kp][1] = __float_as_uint(sm[qb + (g + 8) * ST_ + tg]);
            q_a[u][kp][2] = __float_as_uint(sm[qb + g * ST_ + tg + 4]);
            q_a[u][kp][3] = __float_as_uint(sm[qb + (g + 8) * ST_ + tg + 4]);
        }
    }
    __syncthreads();   // Q staging region free for kv buffers

    // Prefetch kv tile 0 into buf 0
    {
        #pragma unroll
        for (int i = 0; i < 4; i++) {
            int idx = tid + i * 128;
            int r = idx >> 4, c = (idx & 15) * 4;
            cp16(&sm[r * ST_ + c],        kbase + (size_t)r * D_ + c);
            cp16(&sm[2176 + r * ST_ + c], vbase + (size_t)r * D_ + c);
        }
        cp_commit();
    }

    float o[2][8][4] = {};
    float mr[2][2] = {{neg_inf(), neg_inf()}, {neg_inf(), neg_inf()}};
    float lr[2][2] = {};
    int qrow[2];
    qrow[0] = q0 + warp * 32 + g;
    qrow[1] = qrow[0] + 16;

    for (int t = 0; t < NKT_; t++) {
        cp_wait<0>();
        __syncthreads();

        if (t + 1 < NKT_) {
            const float* kb2 = kbase + (size_t)(t + 1) * KT_ * D_;
            const float* vb2 = vbase + (size_t)(t + 1) * KT_ * D_;
            float* dst = sm + ((t + 1) & 1) * 4352;
            #pragma unroll
            for (int i = 0; i < 4; i++) {
                int idx = tid + i * 128;
                int r = idx >> 4, c = (idx & 15) * 4;
                cp16(&dst[r * ST_ + c],        kb2 + (size_t)r * D_ + c);
                cp16(&dst[2176 + r * ST_ + c], vb2 + (size_t)r * D_ + c);
            }
            cp_commit();
        }

        const float* Kc = sm + (t & 1) * 4352;
        const float* Vc = Kc + 2176;
        const int kv0 = t * KT_;
        const int clean = __ldg(fb0 + (t >> 1)) & __ldg(fb1 + (t >> 1));

        // S = Q @ K^T : each K fragment loaded once, feeds both row groups
        float s[2][4][4] = {};
        #pragma unroll
        for (int kp = 0; kp < 8; kp++) {
            #pragma unroll
            for (int nt = 0; nt < 4; nt++) {
                uint32_t bfr[2];
                const int kb = (nt * 8 + g) * ST_ + kp * 8 + tg;
                bfr[0] = __float_as_uint(Kc[kb]);
                bfr[1] = __float_as_uint(Kc[kb + 4]);
                mma8(s[0][nt], q_a[0][kp], bfr);
                mma8(s[1][nt], q_a[1][kp], bfr);
            }
        }

        if (!clean) {
            #pragma unroll
            for (int u = 0; u < 2; u++) {
                #pragma unroll
                for (int nt = 0; nt < 4; nt++) {
                    const int col = kv0 + nt * 8 + 2 * tg;
                    int2 mA = *reinterpret_cast<const int2*>(mbase + (size_t)qrow[u] * N_ + col);
                    int2 mB = *reinterpret_cast<const int2*>(mbase + (size_t)(qrow[u] + 8) * N_ + col);
                    if (!mA.x) s[u][nt][0] = neg_inf();
                    if (!mA.y) s[u][nt][1] = neg_inf();
                    if (!mB.x) s[u][nt][2] = neg_inf();
                    if (!mB.y) s[u][nt][3] = neg_inf();
                }
            }
        }

        // Online softmax (log2 domain), per group u, rows g and g+8
        #pragma unroll
        for (int u = 0; u < 2; u++) {
            float mx0 = neg_inf(), mx1 = neg_inf();
            #pragma unroll
            for (int nt = 0; nt < 4; nt++) {
                mx0 = fmaxf(mx0, fmaxf(s[u][nt][0], s[u][nt][1]));
                mx1 = fmaxf(mx1, fmaxf(s[u][nt][2], s[u][nt][3]));
            }
            mx0 = fmaxf(mx0, __shfl_xor_sync(0xffffffffu, mx0, 1));
            mx0 = fmaxf(mx0, __shfl_xor_sync(0xffffffffu, mx0, 2));
            mx1 = fmaxf(mx1, __shfl_xor_sync(0xffffffffu, mx1, 1));
            mx1 = fmaxf(mx1, __shfl_xor_sync(0xffffffffu, mx1, 2));
            const float mn0 = fmaxf(mr[u][0], mx0), mn1 = fmaxf(mr[u][1], mx1);
            const float sc0 = fexp2(fmaxf(mr[u][0] - mn0, -120.0f));
            const float sc1 = fexp2(fmaxf(mr[u][1] - mn1, -120.0f));
            float sum0 = 0.0f, sum1 = 0.0f;
            #pragma unroll
            for (int nt = 0; nt < 4; nt++) {
                float p0 = f2tf(fexp2(fmaxf(s[u][nt][0] - mn0, -120.0f)));
                float p1 = f2tf(fexp2(fmaxf(s[u][nt][1] - mn0, -120.0f)));
                float p2 = f2tf(fexp2(fmaxf(s[u][nt][2] - mn1, -120.0f)));
                float p3 = f2tf(fexp2(fmaxf(s[u][nt][3] - mn1, -120.0f)));
                s[u][nt][0] = p0; s[u][nt][1] = p1; s[u][nt][2] = p2; s[u][nt][3] = p3;
                sum0 += p0 + p1; sum1 += p2 + p3;
            }
            sum0 += __shfl_xor_sync(0xffffffffu, sum0, 1);
            sum0 += __shfl_xor_sync(0xffffffffu, sum0, 2);
            sum1 += __shfl_xor_sync(0xffffffffu, sum1, 1);
            sum1 += __shfl_xor_sync(0xffffffffu, sum1, 2);
            lr[u][0] = lr[u][0] * sc0 + sum0; lr[u][1] = lr[u][1] * sc1 + sum1;
            mr[u][0] = mn0; mr[u][1] = mn1;

            #pragma unroll
            for (int dt = 0; dt < 8; dt++) {
                o[u][dt][0] *= sc0; o[u][dt][1] *= sc0;
                o[u][dt][2] *= sc1; o[u][dt][3] *= sc1;
            }
        }

        // O += P @ V : each V fragment loaded once, feeds both row groups.
        // P a-frags from c-frags via quad shfls.
        #pragma unroll
        for (int kp = 0; kp < 4; kp++) {
            const int srcA = (g << 2) | (tg >> 1);
            const int srcB = srcA + 2;
            const bool odd = (tg & 1);
            uint32_t a[2][4];
            #pragma unroll
            for (int u = 0; u < 2; u++) {
                float v0 = __shfl_sync(0xffffffffu, s[u][kp][0], srcA);
                float v1 = __shfl_sync(0xffffffffu, s[u][kp][1], srcA);
                float v2 = __shfl_sync(0xffffffffu, s[u][kp][2], srcA);
                float v3 = __shfl_sync(0xffffffffu, s[u][kp][3], srcA);
                float w0 = __shfl_sync(0xffffffffu, s[u][kp][0], srcB);
                float w1 = __shfl_sync(0xffffffffu, s[u][kp][1], srcB);
                float w2 = __shfl_sync(0xffffffffu, s[u][kp][2], srcB);
                float w3 = __shfl_sync(0xffffffffu, s[u][kp][3], srcB);
                a[u][0] = __float_as_uint(odd ? v1 : v0);
                a[u][1] = __float_as_uint(odd ? v3 : v2);
                a[u][2] = __float_as_uint(odd ? w1 : w0);
                a[u][3] = __float_as_uint(odd ? w3 : w2);
            }
            #pragma unroll
            for (int dt = 0; dt < 8; dt++) {
                uint32_t bfr[2];
                const int vb = (kp * 8 + tg) * ST_ + dt * 8 + g;
                bfr[0] = __float_as_uint(Vc[vb]);
                bfr[1] = __float_as_uint(Vc[vb + 4 * ST_]);
                mma8(o[0][dt], a[0], bfr);
                mma8(o[1][dt], a[1], bfr);
            }
        }
    }

    // Epilogue: normalize and recombine heads
    #pragma unroll
    for (int u = 0; u < 2; u++) {
        const float il0 = 1.0f / lr[u][0], il1 = 1.0f / lr[u][1];
        #pragma unroll
        for (int dt = 0; dt < 8; dt++) {
            const int dd = h * 64 + dt * 8 + 2 * tg;
            *reinterpret_cast<float2*>(&g_att[(size_t)(b * N_ + qrow[u]) * E_ + dd]) =
                make_float2(o[u][dt][0] * il0, o[u][dt][1] * il0);
            *reinterpret_cast<float2*>(&g_att[(size_t)(b * N_ + qrow[u] + 8) * E_ + dd]) =
                make_float2(o[u][dt][2] * il1, o[u][dt][3] * il1);
        }
    }
}

// ---------------------------------------------------------------------------
extern "C" void kernel_launch(void* const* d_in, const int* in_sizes, int n_in,
                              void* d_out, int out_size)
{
    const float* Q    = (const float*)d_in[0];
    const float* K    = (const float*)d_in[1];
    const float* V    = (const float*)d_in[2];
    const int*   mask = (const int*)  d_in[3];
    const float* Wq   = (const float*)d_in[4];
    const float* Wk   = (const float*)d_in[5];
    const float* Wv   = (const float*)d_in[6];
    const float* Wo   = (const float*)d_in[7];
    const float* bo   = (const float*)d_in[8];
    const float* tau  = (const float*)d_in[9];
    float* out = (float*)d_out;

    const int gemm_smem = 2 * GBUF_ * (int)sizeof(float);  // 73728

    cudaFuncSetAttribute(gemm_qkv, cudaFuncAttributeMaxDynamicSharedMemorySize, gemm_smem);
    cudaFuncSetAttribute(gemm_out, cudaFuncAttributeMaxDynamicSharedMemorySize, gemm_smem);

    split_w<<<dim3(E_ * E_ / (256 * 4), 4), 256>>>(Wq, Wk, Wv, Wo);
    mask_flags<<<dim3(NT_, NT_, B_), 256>>>(mask);

    gemm_qkv<<<dim3(E_ / 64, M_ / 128, 3), 256, gemm_smem>>>(Q, K, V, tau);

    // grid.x = heads (fastest) so the 8 heads sharing a mask tile are adjacent -> L2 reuse
    attn_tc<<<dim3(H_, N_ / 128, B_), 128>>>(mask);

    gemm_out<<<dim3(E_ / 64, M_ / 128), 256, gemm_smem>>>(bo, out);
}

// round 9
// speedup vs baseline: 3.4220x; 1.1069x over previous
#include <cuda_runtime.h>
#include <cuda_bf16.h>
#include <cstdint>
#include <cstddef>

// Problem constants
constexpr int B_ = 8;
constexpr int N_ = 2048;
constexpr int E_ = 512;
constexpr int H_ = 8;
constexpr int D_ = 64;
constexpr int M_ = B_ * N_;   // 16384 rows
constexpr int NT_ = N_ / 64;  // 32 64-row tiles (mask-flag granularity)
constexpr int KT_ = 32;       // attention kv-tile rows
constexpr int NKT_ = N_ / KT_;// 64 kv tiles
constexpr int ST_ = 68;       // attention smem row stride (floats)

constexpr size_t WBE_ = (size_t)E_ * E_;

// Scratch (device globals: allocation-free per harness rules)
__device__ float g_q[(size_t)B_ * H_ * N_ * D_];   // [b][h][n][d], pre-scaled by log2e/tau, tf32
__device__ float g_k[(size_t)B_ * H_ * N_ * D_];   // tf32-rounded
__device__ float g_v[(size_t)B_ * H_ * N_ * D_];   // tf32-rounded
__device__ float g_att[(size_t)M_ * E_];           // [b*n][h*d] recombined heads
__device__ int   g_mflag[B_ * NT_ * NT_];          // 1 = 64x64 tile all-nonzero
__device__ __nv_bfloat16 g_wbh[4][WBE_];           // bf16 hi parts of Wq,Wk,Wv,Wo
__device__ __nv_bfloat16 g_wbl[4][WBE_];           // bf16 lo parts

__device__ __forceinline__ float neg_inf() { return __int_as_float(0xff800000); }

__device__ __forceinline__ float f2tf(float x) {
    uint32_t r;
    asm("cvt.rna.tf32.f32 %0, %1;" : "=r"(r) : "f"(x));
    return __uint_as_float(r);
}

__device__ __forceinline__ float fexp2(float x) {
    float y;
    asm("ex2.approx.ftz.f32 %0, %1;" : "=f"(y) : "f"(x));
    return y;
}

// m16n8k8 tf32 mma (attention)
__device__ __forceinline__ void mma8(float* c, const uint32_t* a, const uint32_t* b) {
    asm volatile(
        "mma.sync.aligned.m16n8k8.row.col.f32.tf32.tf32.f32 "
        "{%0,%1,%2,%3}, {%4,%5,%6,%7}, {%8,%9}, {%0,%1,%2,%3};\n"
        : "+f"(c[0]), "+f"(c[1]), "+f"(c[2]), "+f"(c[3])
        : "r"(a[0]), "r"(a[1]), "r"(a[2]), "r"(a[3]), "r"(b[0]), "r"(b[1]));
}

// m16n8k16 bf16 mma (projections)
__device__ __forceinline__ void mma16(float* c, const uint32_t* a, const uint32_t* b) {
    asm volatile(
        "mma.sync.aligned.m16n8k16.row.col.f32.bf16.bf16.f32 "
        "{%0,%1,%2,%3}, {%4,%5,%6,%7}, {%8,%9}, {%0,%1,%2,%3};\n"
        : "+f"(c[0]), "+f"(c[1]), "+f"(c[2]), "+f"(c[3])
        : "r"(a[0]), "r"(a[1]), "r"(a[2]), "r"(a[3]), "r"(b[0]), "r"(b[1]));
}

// pack two floats (x0 = smaller k, x1 = larger k) into bf16x2 hi + residual lo
__device__ __forceinline__ void pack_split(float x0, float x1, uint32_t& hi, uint32_t& lo) {
    asm("cvt.rn.bf16x2.f32 %0, %1, %2;" : "=r"(hi) : "f"(x1), "f"(x0));   // hi16=x1, lo16=x0
    float h0 = __uint_as_float(hi << 16);
    float h1 = __uint_as_float(hi & 0xffff0000u);
    asm("cvt.rn.bf16x2.f32 %0, %1, %2;" : "=r"(lo) : "f"(x1 - h1), "f"(x0 - h0));
}

// cp.async helpers
__device__ __forceinline__ void cpb16(const void* smem_dst, const void* gmem_src) {
    uint32_t s = (uint32_t)__cvta_generic_to_shared(smem_dst);
    asm volatile("cp.async.ca.shared.global [%0], [%1], 16;" :: "r"(s), "l"(gmem_src));
}
__device__ __forceinline__ void cp16(const float* smem_dst, const float* gmem_src) {
    cpb16((const void*)smem_dst, (const void*)gmem_src);
}
__device__ __forceinline__ void cp_commit() { asm volatile("cp.async.commit_group;"); }
template<int N>
__device__ __forceinline__ void cp_wait() { asm volatile("cp.async.wait_group %0;" :: "n"(N) : "memory"); }

// ---------------------------------------------------------------------------
// One-time weight split: W -> (hi, lo) bf16 pair. blockIdx.y selects matrix.
// ---------------------------------------------------------------------------
__global__ __launch_bounds__(256)
void split_w(const float* __restrict__ Wq, const float* __restrict__ Wk,
             const float* __restrict__ Wv, const float* __restrict__ Wo)
{
    const int m = blockIdx.y;
    const float* W = (m == 0) ? Wq : (m == 1) ? Wk : (m == 2) ? Wv : Wo;
    const size_t i4 = ((size_t)blockIdx.x * 256 + threadIdx.x) * 4;
    float4 v = *reinterpret_cast<const float4*>(W + i4);
    uint32_t h01, l01, h23, l23;
    pack_split(v.x, v.y, h01, l01);
    pack_split(v.z, v.w, h23, l23);
    *reinterpret_cast<uint2*>(&g_wbh[m][i4]) = make_uint2(h01, h23);
    *reinterpret_cast<uint2*>(&g_wbl[m][i4]) = make_uint2(l01, l23);
}

// ---------------------------------------------------------------------------
// Mask preprocessing: one flag per (b, 64-row q tile, 64-col kv tile).
// ---------------------------------------------------------------------------
__global__ __launch_bounds__(256)
void mask_flags(const int* __restrict__ mask)
{
    const int kvt = blockIdx.x, qt = blockIdx.y, b = blockIdx.z;
    const int tid = threadIdx.x;
    const int r = tid >> 2, c0 = (tid & 3) * 16;
    const int* base = mask + (size_t)b * N_ * N_ + (size_t)(qt * 64 + r) * N_ + kvt * 64 + c0;
    bool ok = true;
    #pragma unroll
    for (int i = 0; i < 4; i++) {
        int4 m = *reinterpret_cast<const int4*>(base + i * 4);
        ok &= (m.x != 0) & (m.y != 0) & (m.z != 0) & (m.w != 0);
    }
    int all = __syncthreads_and((int)ok);
    if (tid == 0) g_mflag[(b * NT_ + qt) * NT_ + kvt] = all;
}

// ---------------------------------------------------------------------------
// GEMM core v3: Y = (Xh+Xl) @ (Wh+Wl)^T, bf16 3-term (Xh Wh + Xh Wl + Xl Wh).
// Block 128x64, BK=32, 256 thr = 8 warps (4m x 2n), warp 32x32, m16n8k16.
// X tile raw fp32 [128][36] (A split to bf16 in regs after LDS.64);
// W tiles bf16 [64][56] hi+lo (stride 56 -> B-frag LDS conflict-free).
// cp.async double buffer.
// ---------------------------------------------------------------------------
constexpr int GXB_ = 128 * 36 * 4;          // X tile bytes (fp32)
constexpr int GWB_ = 64 * 56 * 2;           // one W tile bytes (bf16, stride 56)
constexpr int GBUFB_ = GXB_ + 2 * GWB_;     // 32768 B per buffer
constexpr int GKT_ = E_ / 32;               // 16 k tiles

__device__ __forceinline__ void gemm_prefetch(const float* __restrict__ X, int widx,
                                              char* buf, int m0, int n0, int kt)
{
    const int tid = threadIdx.x;
    float* xs = reinterpret_cast<float*>(buf);
    char* whs = buf + GXB_;
    char* wls = whs + GWB_;
    // X: 128 rows x 32 fp32 = 8 chunks/row of 16B; 1024 chunks, 4/thread
    #pragma unroll
    for (int i = 0; i < 4; i++) {
        int idx = tid + i * 256;
        int r = idx >> 3, c = (idx & 7) * 4;
        cp16(&xs[r * 36 + c], X + (size_t)(m0 + r) * E_ + kt * 32 + c);
    }
    // W: 64 rows x 32 bf16 = 64B/row = 4 chunks; 256 chunks each for hi and lo
    {
        int r = tid >> 2, c = tid & 3;     // c = 16B chunk (8 bf16)
        const __nv_bfloat16* srch = g_wbh[widx] + (size_t)(n0 + r) * E_ + kt * 32 + c * 8;
        const __nv_bfloat16* srcl = g_wbl[widx] + (size_t)(n0 + r) * E_ + kt * 32 + c * 8;
        cpb16(whs + r * 112 + c * 16, srch);
        cpb16(wls + r * 112 + c * 16, srcl);
    }
    cp_commit();
}

__device__ __forceinline__ void gemm_core3(const float* __restrict__ X, int widx,
                                           char* smb, int m0, int n0,
                                           float acc[2][4][4])
{
    const int tid = threadIdx.x;
    const int warp = tid >> 5, lane = tid & 31;
    const int g = lane >> 2, tg = lane & 3;
    const int wm = warp >> 1, wn = warp & 1;

    gemm_prefetch(X, widx, smb, m0, n0, 0);

    for (int kt = 0; kt < GKT_; kt++) {
        if (kt + 1 < GKT_) {
            gemm_prefetch(X, widx, smb + ((kt + 1) & 1) * GBUFB_, m0, n0, kt + 1);
            cp_wait<1>();
        } else {
            cp_wait<0>();
        }
        __syncthreads();
        char* buf = smb + (kt & 1) * GBUFB_;
        const float* Xs = reinterpret_cast<const float*>(buf);
        const char* Whs = buf + GXB_;
        const char* Wls = Whs + GWB_;

        #pragma unroll
        for (int ks = 0; ks < 2; ks++) {
            const int k0 = ks * 16;
            uint32_t Ah[2][4], Al[2][4], Bh[4][2], Bl[4][2];
            #pragma unroll
            for (int mt = 0; mt < 2; mt++) {
                const int rb = (wm * 32 + mt * 16) * 36 + k0;
                // rows g and g+8, k pairs (2tg, 2tg+1) and (8+2tg, 8+2tg+1)
                float2 p0 = *reinterpret_cast<const float2*>(&Xs[rb + g * 36 + 2 * tg]);
                float2 p1 = *reinterpret_cast<const float2*>(&Xs[rb + (g + 8) * 36 + 2 * tg]);
                float2 p2 = *reinterpret_cast<const float2*>(&Xs[rb + g * 36 + 8 + 2 * tg]);
                float2 p3 = *reinterpret_cast<const float2*>(&Xs[rb + (g + 8) * 36 + 8 + 2 * tg]);
                pack_split(p0.x, p0.y, Ah[mt][0], Al[mt][0]);
                pack_split(p1.x, p1.y, Ah[mt][1], Al[mt][1]);
                pack_split(p2.x, p2.y, Ah[mt][2], Al[mt][2]);
                pack_split(p3.x, p3.y, Ah[mt][3], Al[mt][3]);
            }
            #pragma unroll
            for (int nt = 0; nt < 4; nt++) {
                const int r = wn * 32 + nt * 8 + g;
                const int boff = r * 112 + (k0 + 2 * tg) * 2;
                Bh[nt][0] = *reinterpret_cast<const uint32_t*>(Whs + boff);
                Bh[nt][1] = *reinterpret_cast<const uint32_t*>(Whs + boff + 16);
                Bl[nt][0] = *reinterpret_cast<const uint32_t*>(Wls + boff);
                Bl[nt][1] = *reinterpret_cast<const uint32_t*>(Wls + boff + 16);
            }
            #pragma unroll
            for (int mt = 0; mt < 2; mt++)
                #pragma unroll
                for (int nt = 0; nt < 4; nt++) {
                    mma16(acc[mt][nt], Ah[mt], Bh[nt]);   // hi*hi
                    mma16(acc[mt][nt], Ah[mt], Bl[nt]);   // hi*lo
                    mma16(acc[mt][nt], Al[mt], Bh[nt]);   // lo*hi
                }
        }
        __syncthreads();
    }
}

// QKV projections fused; outputs pre-formatted for attention.
__global__ __launch_bounds__(256)
void gemm_qkv(const float* __restrict__ Qi, const float* __restrict__ Ki,
              const float* __restrict__ Vi, const float* __restrict__ taup)
{
    extern __shared__ char smb[];
    const int z = blockIdx.z;
    const float* X = (z == 0) ? Qi : (z == 1) ? Ki : Vi;
    float* Y = (z == 0) ? g_q : (z == 1) ? g_k : g_v;
    const float scl = (z == 0) ? (1.4426950408889634f / __ldg(taup)) : 1.0f;

    const int m0 = blockIdx.y * 128, n0 = blockIdx.x * 64;
    float acc[2][4][4] = {};
    gemm_core3(X, z, smb, m0, n0, acc);

    const int tid = threadIdx.x;
    const int warp = tid >> 5, lane = tid & 31;
    const int g = lane >> 2, tg = lane & 3;
    const int wm = warp >> 1, wn = warp & 1;
    const int h = blockIdx.x;              // BN=64 == head dim
    #pragma unroll
    for (int mt = 0; mt < 2; mt++) {
        #pragma unroll
        for (int nt = 0; nt < 4; nt++) {
            const int dd = wn * 32 + nt * 8 + 2 * tg;
            int m = m0 + wm * 32 + mt * 16 + g;
            int b = m >> 11, n = m & (N_ - 1);
            *reinterpret_cast<float2*>(&Y[((size_t)((b * H_ + h) * N_ + n)) * D_ + dd]) =
                make_float2(f2tf(acc[mt][nt][0] * scl), f2tf(acc[mt][nt][1] * scl));
            m += 8; b = m >> 11; n = m & (N_ - 1);
            *reinterpret_cast<float2*>(&Y[((size_t)((b * H_ + h) * N_ + n)) * D_ + dd]) =
                make_float2(f2tf(acc[mt][nt][2] * scl), f2tf(acc[mt][nt][3] * scl));
        }
    }
}

// Output projection: g_att @ Wo^T + bo -> out
__global__ __launch_bounds__(256)
void gemm_out(const float* __restrict__ bias, float* __restrict__ Yext)
{
    extern __shared__ char smb[];
    const int m0 = blockIdx.y * 128, n0 = blockIdx.x * 64;
    float acc[2][4][4] = {};
    gemm_core3(g_att, 3, smb, m0, n0, acc);

    const int tid = threadIdx.x;
    const int warp = tid >> 5, lane = tid & 31;
    const int g = lane >> 2, tg = lane & 3;
    const int wm = warp >> 1, wn = warp & 1;
    #pragma unroll
    for (int mt = 0; mt < 2; mt++) {
        #pragma unroll
        for (int nt = 0; nt < 4; nt++) {
            const int o = n0 + wn * 32 + nt * 8 + 2 * tg;
            float2 bb = *reinterpret_cast<const float2*>(bias + o);
            const int m = m0 + wm * 32 + mt * 16 + g;
            *reinterpret_cast<float2*>(&Yext[(size_t)m * E_ + o]) =
                make_float2(acc[mt][nt][0] + bb.x, acc[mt][nt][1] + bb.y);
            *reinterpret_cast<float2*>(&Yext[(size_t)(m + 8) * E_ + o]) =
                make_float2(acc[mt][nt][2] + bb.x, acc[mt][nt][3] + bb.y);
        }
    }
}

// ---------------------------------------------------------------------------
// Flash attention v4 (unchanged from R8): 128 q-rows per block, 4 warps x 32
// rows (two 16-row mma groups). K/V fragments loaded once, feed both groups.
// cp.async double-buffered kv tiles of 32; P via quad shfls; log2 softmax.
// ---------------------------------------------------------------------------
__global__ __launch_bounds__(128, 2)
void attn_tc(const int* __restrict__ mask)
{
    __shared__ float sm[4 * KT_ * ST_];   // 34816 B

    const int h = blockIdx.x, qt = blockIdx.y, b = blockIdx.z;
    const int tid = threadIdx.x;
    const int warp = tid >> 5, lane = tid & 31;
    const int g = lane >> 2, tg = lane & 3;
    const int q0 = qt * 128;

    const size_t bh = (size_t)(b * H_ + h) * N_ * D_;
    const float* qbase = g_q + bh;
    const float* kbase = g_k + bh;
    const float* vbase = g_v + bh;
    const int* mbase = mask + (size_t)b * N_ * N_;
    const int* fb0 = g_mflag + (b * NT_ + 2 * qt) * NT_;
    const int* fb1 = fb0 + NT_;

    // Stage Q (128x64, already scaled+tf32) through the buffer region
    {
        #pragma unroll
        for (int i = 0; i < 16; i++) {
            int idx = tid + i * 128;
            int r = idx >> 4, c = (idx & 15) * 4;
            cp16(&sm[r * ST_ + c], qbase + (size_t)(q0 + r) * D_ + c);
        }
        cp_commit(); cp_wait<0>();
        __syncthreads();
    }

    uint32_t q_a[2][8][4];
    #pragma unroll
    for (int u = 0; u < 2; u++) {
        #pragma unroll
        for (int kp = 0; kp < 8; kp++) {
            const int qb = (warp * 32 + u * 16) * ST_ + kp * 8;
            q_a[u][kp][0] = __float_as_uint(sm[qb + g * ST_ + tg]);
            q_a[u][kp][1] = __float_as_uint(sm[qb + (g + 8) * ST_ + tg]);
            q_a[u][kp][2] = __float_as_uint(sm[qb + g * ST_ + tg + 4]);
            q_a[u][kp][3] = __float_as_uint(sm[qb + (g + 8) * ST_ + tg + 4]);
        }
    }
    __syncthreads();

    {
        #pragma unroll
        for (int i = 0; i < 4; i++) {
            int idx = tid + i * 128;
            int r = idx >> 4, c = (idx & 15) * 4;
            cp16(&sm[r * ST_ + c],        kbase + (size_t)r * D_ + c);
            cp16(&sm[2176 + r * ST_ + c], vbase + (size_t)r * D_ + c);
        }
        cp_commit();
    }

    float o[2][8][4] = {};
    float mr[2][2] = {{neg_inf(), neg_inf()}, {neg_inf(), neg_inf()}};
    float lr[2][2] = {};
    int qrow[2];
    qrow[0] = q0 + warp * 32 + g;
    qrow[1] = qrow[0] + 16;

    for (int t = 0; t < NKT_; t++) {
        cp_wait<0>();
        __syncthreads();

        if (t + 1 < NKT_) {
            const float* kb2 = kbase + (size_t)(t + 1) * KT_ * D_;
            const float* vb2 = vbase + (size_t)(t + 1) * KT_ * D_;
            float* dst = sm + ((t + 1) & 1) * 4352;
            #pragma unroll
            for (int i = 0; i < 4; i++) {
                int idx = tid + i * 128;
                int r = idx >> 4, c = (idx & 15) * 4;
                cp16(&dst[r * ST_ + c],        kb2 + (size_t)r * D_ + c);
                cp16(&dst[2176 + r * ST_ + c], vb2 + (size_t)r * D_ + c);
            }
            cp_commit();
        }

        const float* Kc = sm + (t & 1) * 4352;
        const float* Vc = Kc + 2176;
        const int kv0 = t * KT_;
        const int clean = __ldg(fb0 + (t >> 1)) & __ldg(fb1 + (t >> 1));

        float s[2][4][4] = {};
        #pragma unroll
        for (int kp = 0; kp < 8; kp++) {
            #pragma unroll
            for (int nt = 0; nt < 4; nt++) {
                uint32_t bfr[2];
                const int kb = (nt * 8 + g) * ST_ + kp * 8 + tg;
                bfr[0] = __float_as_uint(Kc[kb]);
                bfr[1] = __float_as_uint(Kc[kb + 4]);
                mma8(s[0][nt], q_a[0][kp], bfr);
                mma8(s[1][nt], q_a[1][kp], bfr);
            }
        }

        if (!clean) {
            #pragma unroll
            for (int u = 0; u < 2; u++) {
                #pragma unroll
                for (int nt = 0; nt < 4; nt++) {
                    const int col = kv0 + nt * 8 + 2 * tg;
                    int2 mA = *reinterpret_cast<const int2*>(mbase + (size_t)qrow[u] * N_ + col);
                    int2 mB = *reinterpret_cast<const int2*>(mbase + (size_t)(qrow[u] + 8) * N_ + col);
                    if (!mA.x) s[u][nt][0] = neg_inf();
                    if (!mA.y) s[u][nt][1] = neg_inf();
                    if (!mB.x) s[u][nt][2] = neg_inf();
                    if (!mB.y) s[u][nt][3] = neg_inf();
                }
            }
        }

        #pragma unroll
        for (int u = 0; u < 2; u++) {
            float mx0 = neg_inf(), mx1 = neg_inf();
            #pragma unroll
            for (int nt = 0; nt < 4; nt++) {
                mx0 = fmaxf(mx0, fmaxf(s[u][nt][0], s[u][nt][1]));
                mx1 = fmaxf(mx1, fmaxf(s[u][nt][2], s[u][nt][3]));
            }
            mx0 = fmaxf(mx0, __shfl_xor_sync(0xffffffffu, mx0, 1));
            mx0 = fmaxf(mx0, __shfl_xor_sync(0xffffffffu, mx0, 2));
            mx1 = fmaxf(mx1, __shfl_xor_sync(0xffffffffu, mx1, 1));
            mx1 = fmaxf(mx1, __shfl_xor_sync(0xffffffffu, mx1, 2));
            const float mn0 = fmaxf(mr[u][0], mx0), mn1 = fmaxf(mr[u][1], mx1);
            const float sc0 = fexp2(fmaxf(mr[u][0] - mn0, -120.0f));
            const float sc1 = fexp2(fmaxf(mr[u][1] - mn1, -120.0f));
            float sum0 = 0.0f, sum1 = 0.0f;
            #pragma unroll
            for (int nt = 0; nt < 4; nt++) {
                float p0 = f2tf(fexp2(fmaxf(s[u][nt][0] - mn0, -120.0f)));
                float p1 = f2tf(fexp2(fmaxf(s[u][nt][1] - mn0, -120.0f)));
                float p2 = f2tf(fexp2(fmaxf(s[u][nt][2] - mn1, -120.0f)));
                float p3 = f2tf(fexp2(fmaxf(s[u][nt][3] - mn1, -120.0f)));
                s[u][nt][0] = p0; s[u][nt][1] = p1; s[u][nt][2] = p2; s[u][nt][3] = p3;
                sum0 += p0 + p1; sum1 += p2 + p3;
            }
            sum0 += __shfl_xor_sync(0xffffffffu, sum0, 1);
            sum0 += __shfl_xor_sync(0xffffffffu, sum0, 2);
            sum1 += __shfl_xor_sync(0xffffffffu, sum1, 1);
            sum1 += __shfl_xor_sync(0xffffffffu, sum1, 2);
            lr[u][0] = lr[u][0] * sc0 + sum0; lr[u][1] = lr[u][1] * sc1 + sum1;
            mr[u][0] = mn0; mr[u][1] = mn1;

            #pragma unroll
            for (int dt = 0; dt < 8; dt++) {
                o[u][dt][0] *= sc0; o[u][dt][1] *= sc0;
                o[u][dt][2] *= sc1; o[u][dt][3] *= sc1;
            }
        }

        #pragma unroll
        for (int kp = 0; kp < 4; kp++) {
            const int srcA = (g << 2) | (tg >> 1);
            const int srcB = srcA + 2;
            const bool odd = (tg & 1);
            uint32_t a[2][4];
            #pragma unroll
            for (int u = 0; u < 2; u++) {
                float v0 = __shfl_sync(0xffffffffu, s[u][kp][0], srcA);
                float v1 = __shfl_sync(0xffffffffu, s[u][kp][1], srcA);
                float v2 = __shfl_sync(0xffffffffu, s[u][kp][2], srcA);
                float v3 = __shfl_sync(0xffffffffu, s[u][kp][3], srcA);
                float w0 = __shfl_sync(0xffffffffu, s[u][kp][0], srcB);
                float w1 = __shfl_sync(0xffffffffu, s[u][kp][1], srcB);
                float w2 = __shfl_sync(0xffffffffu, s[u][kp][2], srcB);
                float w3 = __shfl_sync(0xffffffffu, s[u][kp][3], srcB);
                a[u][0] = __float_as_uint(odd ? v1 : v0);
                a[u][1] = __float_as_uint(odd ? v3 : v2);
                a[u][2] = __float_as_uint(odd ? w1 : w0);
                a[u][3] = __float_as_uint(odd ? w3 : w2);
            }
            #pragma unroll
            for (int dt = 0; dt < 8; dt++) {
                uint32_t bfr[2];
                const int vb = (kp * 8 + tg) * ST_ + dt * 8 + g;
                bfr[0] = __float_as_uint(Vc[vb]);
                bfr[1] = __float_as_uint(Vc[vb + 4 * ST_]);
                mma8(o[0][dt], a[0], bfr);
                mma8(o[1][dt], a[1], bfr);
            }
        }
    }

    #pragma unroll
    for (int u = 0; u < 2; u++) {
        const float il0 = 1.0f / lr[u][0], il1 = 1.0f / lr[u][1];
        #pragma unroll
        for (int dt = 0; dt < 8; dt++) {
            const int dd = h * 64 + dt * 8 + 2 * tg;
            *reinterpret_cast<float2*>(&g_att[(size_t)(b * N_ + qrow[u]) * E_ + dd]) =
                make_float2(o[u][dt][0] * il0, o[u][dt][1] * il0);
            *reinterpret_cast<float2*>(&g_att[(size_t)(b * N_ + qrow[u] + 8) * E_ + dd]) =
                make_float2(o[u][dt][2] * il1, o[u][dt][3] * il1);
        }
    }
}

// ---------------------------------------------------------------------------
extern "C" void kernel_launch(void* const* d_in, const int* in_sizes, int n_in,
                              void* d_out, int out_size)
{
    const float* Q    = (const float*)d_in[0];
    const float* K    = (const float*)d_in[1];
    const float* V    = (const float*)d_in[2];
    const int*   mask = (const int*)  d_in[3];
    const float* Wq   = (const float*)d_in[4];
    const float* Wk   = (const float*)d_in[5];
    const float* Wv   = (const float*)d_in[6];
    const float* Wo   = (const float*)d_in[7];
    const float* bo   = (const float*)d_in[8];
    const float* tau  = (const float*)d_in[9];
    float* out = (float*)d_out;

    const int gemm_smem = 2 * GBUFB_;   // 65536

    cudaFuncSetAttribute(gemm_qkv, cudaFuncAttributeMaxDynamicSharedMemorySize, gemm_smem);
    cudaFuncSetAttribute(gemm_out, cudaFuncAttributeMaxDynamicSharedMemorySize, gemm_smem);

    split_w<<<dim3((int)(WBE_ / 1024), 4), 256>>>(Wq, Wk, Wv, Wo);
    mask_flags<<<dim3(NT_, NT_, B_), 256>>>(mask);

    gemm_qkv<<<dim3(E_ / 64, M_ / 128, 3), 256, gemm_smem>>>(Q, K, V, tau);

    // grid.x = heads (fastest) so the 8 heads sharing a mask tile are adjacent -> L2 reuse
    attn_tc<<<dim3(H_, N_ / 128, B_), 128>>>(mask);

    gemm_out<<<dim3(E_ / 64, M_ / 128), 256, gemm_smem>>>(bo, out);
}

// round 10
// speedup vs baseline: 4.2639x; 1.2460x over previous
#include <cuda_runtime.h>
#include <cuda_bf16.h>
#include <cuda_fp16.h>
#include <cstdint>
#include <cstddef>

// Problem constants
constexpr int B_ = 8;
constexpr int N_ = 2048;
constexpr int E_ = 512;
constexpr int H_ = 8;
constexpr int D_ = 64;
constexpr int M_ = B_ * N_;   // 16384 rows
constexpr int NT_ = N_ / 64;  // 32 64-row tiles (mask-flag granularity)
constexpr int KT_ = 32;       // attention kv-tile rows
constexpr int NKT_ = N_ / KT_;// 64 kv tiles
constexpr int KST_ = 72;      // K/Q smem row stride (halfs): conflict-free frag LDS
constexpr int VST_ = 40;      // Vt smem row stride (halfs): conflict-free frag LDS
constexpr int BUFH_ = 32 * KST_ + 64 * VST_;   // 4864 halfs per KV buffer

constexpr size_t WBE_ = (size_t)E_ * E_;

// Scratch (device globals: allocation-free per harness rules)
__device__ __half g_qh[(size_t)B_ * H_ * N_ * D_];  // [b][h][n][d], pre-scaled log2e/tau, fp16
__device__ __half g_kh[(size_t)B_ * H_ * N_ * D_];  // [b][h][n][d] fp16
__device__ __half g_vt[(size_t)B_ * H_ * D_ * N_];  // [b][h][d][n] fp16 (V transposed)
__device__ float  g_att[(size_t)M_ * E_];           // [b*n][h*d] recombined heads
__device__ int    g_mflag[B_ * NT_ * NT_];          // 1 = 64x64 tile all-nonzero
__device__ __nv_bfloat16 g_wbh[4][WBE_];            // bf16 hi parts of Wq,Wk,Wv,Wo
__device__ __nv_bfloat16 g_wbl[4][WBE_];            // bf16 lo parts

__device__ __forceinline__ float neg_inf() { return __int_as_float(0xff800000); }

__device__ __forceinline__ float fexp2(float x) {
    float y;
    asm("ex2.approx.ftz.f32 %0, %1;" : "=f"(y) : "f"(x));
    return y;
}

// pack two floats into f16x2 (hi half = first arg)
__device__ __forceinline__ uint32_t packh(float hi, float lo) {
    uint32_t r;
    asm("cvt.rn.f16x2.f32 %0, %1, %2;" : "=r"(r) : "f"(hi), "f"(lo));
    return r;
}

// m16n8k16 bf16 mma (projections)
__device__ __forceinline__ void mma16b(float* c, const uint32_t* a, const uint32_t* b) {
    asm volatile(
        "mma.sync.aligned.m16n8k16.row.col.f32.bf16.bf16.f32 "
        "{%0,%1,%2,%3}, {%4,%5,%6,%7}, {%8,%9}, {%0,%1,%2,%3};\n"
        : "+f"(c[0]), "+f"(c[1]), "+f"(c[2]), "+f"(c[3])
        : "r"(a[0]), "r"(a[1]), "r"(a[2]), "r"(a[3]), "r"(b[0]), "r"(b[1]));
}

// m16n8k16 fp16 mma, fp32 accumulate (attention)
__device__ __forceinline__ void mma16h(float* c, const uint32_t* a, const uint32_t* b) {
    asm volatile(
        "mma.sync.aligned.m16n8k16.row.col.f32.f16.f16.f32 "
        "{%0,%1,%2,%3}, {%4,%5,%6,%7}, {%8,%9}, {%0,%1,%2,%3};\n"
        : "+f"(c[0]), "+f"(c[1]), "+f"(c[2]), "+f"(c[3])
        : "r"(a[0]), "r"(a[1]), "r"(a[2]), "r"(a[3]), "r"(b[0]), "r"(b[1]));
}

// pack two floats into bf16x2 hi + residual lo (projection weight/act split)
__device__ __forceinline__ void pack_split(float x0, float x1, uint32_t& hi, uint32_t& lo) {
    asm("cvt.rn.bf16x2.f32 %0, %1, %2;" : "=r"(hi) : "f"(x1), "f"(x0));   // hi16=x1, lo16=x0
    float h0 = __uint_as_float(hi << 16);
    float h1 = __uint_as_float(hi & 0xffff0000u);
    asm("cvt.rn.bf16x2.f32 %0, %1, %2;" : "=r"(lo) : "f"(x1 - h1), "f"(x0 - h0));
}

// cp.async helpers
__device__ __forceinline__ void cpb16(const void* smem_dst, const void* gmem_src) {
    uint32_t s = (uint32_t)__cvta_generic_to_shared(smem_dst);
    asm volatile("cp.async.ca.shared.global [%0], [%1], 16;" :: "r"(s), "l"(gmem_src));
}
__device__ __forceinline__ void cp_commit() { asm volatile("cp.async.commit_group;"); }
template<int N>
__device__ __forceinline__ void cp_wait() { asm volatile("cp.async.wait_group %0;" :: "n"(N) : "memory"); }

// ---------------------------------------------------------------------------
// One-time weight split: W -> (hi, lo) bf16 pair. blockIdx.y selects matrix.
// ---------------------------------------------------------------------------
__global__ __launch_bounds__(256)
void split_w(const float* __restrict__ Wq, const float* __restrict__ Wk,
             const float* __restrict__ Wv, const float* __restrict__ Wo)
{
    const int m = blockIdx.y;
    const float* W = (m == 0) ? Wq : (m == 1) ? Wk : (m == 2) ? Wv : Wo;
    const size_t i4 = ((size_t)blockIdx.x * 256 + threadIdx.x) * 4;
    float4 v = *reinterpret_cast<const float4*>(W + i4);
    uint32_t h01, l01, h23, l23;
    pack_split(v.x, v.y, h01, l01);
    pack_split(v.z, v.w, h23, l23);
    *reinterpret_cast<uint2*>(&g_wbh[m][i4]) = make_uint2(h01, h23);
    *reinterpret_cast<uint2*>(&g_wbl[m][i4]) = make_uint2(l01, l23);
}

// ---------------------------------------------------------------------------
// Mask preprocessing: one flag per (b, 64-row q tile, 64-col kv tile).
// ---------------------------------------------------------------------------
__global__ __launch_bounds__(256)
void mask_flags(const int* __restrict__ mask)
{
    const int kvt = blockIdx.x, qt = blockIdx.y, b = blockIdx.z;
    const int tid = threadIdx.x;
    const int r = tid >> 2, c0 = (tid & 3) * 16;
    const int* base = mask + (size_t)b * N_ * N_ + (size_t)(qt * 64 + r) * N_ + kvt * 64 + c0;
    bool ok = true;
    #pragma unroll
    for (int i = 0; i < 4; i++) {
        int4 m = *reinterpret_cast<const int4*>(base + i * 4);
        ok &= (m.x != 0) & (m.y != 0) & (m.z != 0) & (m.w != 0);
    }
    int all = __syncthreads_and((int)ok);
    if (tid == 0) g_mflag[(b * NT_ + qt) * NT_ + kvt] = all;
}

// ---------------------------------------------------------------------------
// GEMM core (R9, validated): Y = (Xh+Xl)@(Wh+Wl)^T, bf16 3-term, m16n8k16.
// Block 128x64, BK=32, 256 thr = 8 warps (4m x 2n), warp 32x32.
// ---------------------------------------------------------------------------
constexpr int GXB_ = 128 * 36 * 4;          // X tile bytes (fp32)
constexpr int GWB_ = 64 * 56 * 2;           // one W tile bytes (bf16, stride 56)
constexpr int GBUFB_ = GXB_ + 2 * GWB_;     // 32768 B per buffer
constexpr int GKT_ = E_ / 32;               // 16 k tiles

__device__ __forceinline__ void cp16f(const float* smem_dst, const float* gmem_src) {
    cpb16((const void*)smem_dst, (const void*)gmem_src);
}

__device__ __forceinline__ void gemm_prefetch(const float* __restrict__ X, int widx,
                                              char* buf, int m0, int n0, int kt)
{
    const int tid = threadIdx.x;
    float* xs = reinterpret_cast<float*>(buf);
    char* whs = buf + GXB_;
    char* wls = whs + GWB_;
    #pragma unroll
    for (int i = 0; i < 4; i++) {
        int idx = tid + i * 256;
        int r = idx >> 3, c = (idx & 7) * 4;
        cp16f(&xs[r * 36 + c], X + (size_t)(m0 + r) * E_ + kt * 32 + c);
    }
    {
        int r = tid >> 2, c = tid & 3;
        const __nv_bfloat16* srch = g_wbh[widx] + (size_t)(n0 + r) * E_ + kt * 32 + c * 8;
        const __nv_bfloat16* srcl = g_wbl[widx] + (size_t)(n0 + r) * E_ + kt * 32 + c * 8;
        cpb16(whs + r * 112 + c * 16, srch);
        cpb16(wls + r * 112 + c * 16, srcl);
    }
    cp_commit();
}

__device__ __forceinline__ void gemm_core3(const float* __restrict__ X, int widx,
                                           char* smb, int m0, int n0,
                                           float acc[2][4][4])
{
    const int tid = threadIdx.x;
    const int warp = tid >> 5, lane = tid & 31;
    const int g = lane >> 2, tg = lane & 3;
    const int wm = warp >> 1, wn = warp & 1;

    gemm_prefetch(X, widx, smb, m0, n0, 0);

    for (int kt = 0; kt < GKT_; kt++) {
        if (kt + 1 < GKT_) {
            gemm_prefetch(X, widx, smb + ((kt + 1) & 1) * GBUFB_, m0, n0, kt + 1);
            cp_wait<1>();
        } else {
            cp_wait<0>();
        }
        __syncthreads();
        char* buf = smb + (kt & 1) * GBUFB_;
        const float* Xs = reinterpret_cast<const float*>(buf);
        const char* Whs = buf + GXB_;
        const char* Wls = Whs + GWB_;

        #pragma unroll
        for (int ks = 0; ks < 2; ks++) {
            const int k0 = ks * 16;
            uint32_t Ah[2][4], Al[2][4], Bh[4][2], Bl[4][2];
            #pragma unroll
            for (int mt = 0; mt < 2; mt++) {
                const int rb = (wm * 32 + mt * 16) * 36 + k0;
                float2 p0 = *reinterpret_cast<const float2*>(&Xs[rb + g * 36 + 2 * tg]);
                float2 p1 = *reinterpret_cast<const float2*>(&Xs[rb + (g + 8) * 36 + 2 * tg]);
                float2 p2 = *reinterpret_cast<const float2*>(&Xs[rb + g * 36 + 8 + 2 * tg]);
                float2 p3 = *reinterpret_cast<const float2*>(&Xs[rb + (g + 8) * 36 + 8 + 2 * tg]);
                pack_split(p0.x, p0.y, Ah[mt][0], Al[mt][0]);
                pack_split(p1.x, p1.y, Ah[mt][1], Al[mt][1]);
                pack_split(p2.x, p2.y, Ah[mt][2], Al[mt][2]);
                pack_split(p3.x, p3.y, Ah[mt][3], Al[mt][3]);
            }
            #pragma unroll
            for (int nt = 0; nt < 4; nt++) {
                const int r = wn * 32 + nt * 8 + g;
                const int boff = r * 112 + (k0 + 2 * tg) * 2;
                Bh[nt][0] = *reinterpret_cast<const uint32_t*>(Whs + boff);
                Bh[nt][1] = *reinterpret_cast<const uint32_t*>(Whs + boff + 16);
                Bl[nt][0] = *reinterpret_cast<const uint32_t*>(Wls + boff);
                Bl[nt][1] = *reinterpret_cast<const uint32_t*>(Wls + boff + 16);
            }
            #pragma unroll
            for (int mt = 0; mt < 2; mt++)
                #pragma unroll
                for (int nt = 0; nt < 4; nt++) {
                    mma16b(acc[mt][nt], Ah[mt], Bh[nt]);
                    mma16b(acc[mt][nt], Ah[mt], Bl[nt]);
                    mma16b(acc[mt][nt], Al[mt], Bh[nt]);
                }
        }
        __syncthreads();
    }
}

// QKV projections fused; outputs fp16 formatted for the fp16 attention:
//  z=0: Q scaled by log2e/tau -> g_qh [b][h][n][d]
//  z=1: K -> g_kh [b][h][n][d]
//  z=2: V -> g_vt [b][h][d][n]  (transposed via smem)
__global__ __launch_bounds__(256)
void gemm_qkv(const float* __restrict__ Qi, const float* __restrict__ Ki,
              const float* __restrict__ Vi, const float* __restrict__ taup)
{
    extern __shared__ char smb[];
    const int z = blockIdx.z;
    const float* X = (z == 0) ? Qi : (z == 1) ? Ki : Vi;
    const float scl = (z == 0) ? (1.4426950408889634f / __ldg(taup)) : 1.0f;

    const int m0 = blockIdx.y * 128, n0 = blockIdx.x * 64;
    float acc[2][4][4] = {};
    gemm_core3(X, z, smb, m0, n0, acc);

    const int tid = threadIdx.x;
    const int warp = tid >> 5, lane = tid & 31;
    const int g = lane >> 2, tg = lane & 3;
    const int wm = warp >> 1, wn = warp & 1;
    const int h = blockIdx.x;              // BN=64 == head dim

    if (z <= 1) {
        __half* Y = (z == 0) ? g_qh : g_kh;
        #pragma unroll
        for (int mt = 0; mt < 2; mt++) {
            #pragma unroll
            for (int nt = 0; nt < 4; nt++) {
                const int dd = wn * 32 + nt * 8 + 2 * tg;
                int m = m0 + wm * 32 + mt * 16 + g;
                int b = m >> 11, n = m & (N_ - 1);
                *reinterpret_cast<uint32_t*>(&Y[((size_t)((b * H_ + h) * N_ + n)) * D_ + dd]) =
                    packh(acc[mt][nt][1] * scl, acc[mt][nt][0] * scl);
                m += 8; b = m >> 11; n = m & (N_ - 1);
                *reinterpret_cast<uint32_t*>(&Y[((size_t)((b * H_ + h) * N_ + n)) * D_ + dd]) =
                    packh(acc[mt][nt][3] * scl, acc[mt][nt][2] * scl);
            }
        }
    } else {
        // V: transpose 128(m) x 64(d) tile through smem -> g_vt[b][h][d][n]
        __half* ts = reinterpret_cast<__half*>(smb);   // [64][136] halfs
        __syncthreads();   // gemm buffers done
        #pragma unroll
        for (int mt = 0; mt < 2; mt++) {
            #pragma unroll
            for (int nt = 0; nt < 4; nt++) {
                const int dd = wn * 32 + nt * 8 + 2 * tg;
                const int ml = wm * 32 + mt * 16 + g;
                ts[dd * 136 + ml]           = __float2half(acc[mt][nt][0]);
                ts[(dd + 1) * 136 + ml]     = __float2half(acc[mt][nt][1]);
                ts[dd * 136 + ml + 8]       = __float2half(acc[mt][nt][2]);
                ts[(dd + 1) * 136 + ml + 8] = __float2half(acc[mt][nt][3]);
            }
        }
        __syncthreads();
        const int r = tid >> 2, c = tid & 3;
        const int bb = m0 >> 11, noff = m0 & (N_ - 1);
        __half* dst = g_vt + ((size_t)((bb * H_ + h) * D_ + r)) * N_ + noff + c * 32;
        #pragma unroll
        for (int i = 0; i < 4; i++)
            *reinterpret_cast<uint4*>(dst + i * 8) =
                *reinterpret_cast<const uint4*>(&ts[r * 136 + c * 32 + i * 8]);
    }
}

// Output projection: g_att @ Wo^T + bo -> out
__global__ __launch_bounds__(256)
void gemm_out(const float* __restrict__ bias, float* __restrict__ Yext)
{
    extern __shared__ char smb[];
    const int m0 = blockIdx.y * 128, n0 = blockIdx.x * 64;
    float acc[2][4][4] = {};
    gemm_core3(g_att, 3, smb, m0, n0, acc);

    const int tid = threadIdx.x;
    const int warp = tid >> 5, lane = tid & 31;
    const int g = lane >> 2, tg = lane & 3;
    const int wm = warp >> 1, wn = warp & 1;
    #pragma unroll
    for (int mt = 0; mt < 2; mt++) {
        #pragma unroll
        for (int nt = 0; nt < 4; nt++) {
            const int o = n0 + wn * 32 + nt * 8 + 2 * tg;
            float2 bb = *reinterpret_cast<const float2*>(bias + o);
            const int m = m0 + wm * 32 + mt * 16 + g;
            *reinterpret_cast<float2*>(&Yext[(size_t)m * E_ + o]) =
                make_float2(acc[mt][nt][0] + bb.x, acc[mt][nt][1] + bb.y);
            *reinterpret_cast<float2*>(&Yext[(size_t)(m + 8) * E_ + o]) =
                make_float2(acc[mt][nt][2] + bb.x, acc[mt][nt][3] + bb.y);
        }
    }
}

// ---------------------------------------------------------------------------
// Flash attention v5: fp16 m16n8k16 (2x MAC density vs tf32 k8, same 11-bit
// precision). 128 q-rows per block, 4 warps x 32 rows (u=0,1 groups); K/V
// fragments loaded once, feed both groups. K [kv][d] fp16 smem stride 72;
// V transposed [d][kv] stride 40 -> all frag LDS conflict-free. cp.async
// double buffer; P c-frag -> fp16 a-frag via quad shfls + f16x2 packs.
// ---------------------------------------------------------------------------
__global__ __launch_bounds__(128, 2)
void attn_tc(const int* __restrict__ mask)
{
    __shared__ __align__(16) __half sm[2 * BUFH_];   // 19456 B; Q staged here first

    const int h = blockIdx.x, qt = blockIdx.y, b = blockIdx.z;
    const int tid = threadIdx.x;
    const int warp = tid >> 5, lane = tid & 31;
    const int g = lane >> 2, tg = lane & 3;
    const int q0 = qt * 128;

    const size_t bh = (size_t)(b * H_ + h) * N_ * D_;
    const __half* qbase = g_qh + bh;
    const __half* kbase = g_kh + bh;
    const __half* vtbase = g_vt + bh;      // [d][n] layout, same element count
    const int* mbase = mask + (size_t)b * N_ * N_;
    const int* fb0 = g_mflag + (b * NT_ + 2 * qt) * NT_;
    const int* fb1 = fb0 + NT_;

    // ---- Stage Q (128x64 fp16) into smem [128][72] ----
    {
        #pragma unroll
        for (int i = 0; i < 8; i++) {
            int idx = tid + i * 128;             // 0..1023
            int r = idx >> 3, c = (idx & 7) * 8;
            cpb16(&sm[r * KST_ + c], qbase + (size_t)(q0 + r) * D_ + c);
        }
        cp_commit(); cp_wait<0>();
        __syncthreads();
    }

    // Hoist Q a-frags (fp16 k16): q_a[u][kc][0..3]
    uint32_t q_a[2][4][4];
    #pragma unroll
    for (int u = 0; u < 2; u++) {
        #pragma unroll
        for (int kc = 0; kc < 4; kc++) {
            const int row = warp * 32 + u * 16 + g;
            q_a[u][kc][0] = *reinterpret_cast<const uint32_t*>(&sm[row * KST_ + kc * 16 + 2 * tg]);
            q_a[u][kc][1] = *reinterpret_cast<const uint32_t*>(&sm[(row + 8) * KST_ + kc * 16 + 2 * tg]);
            q_a[u][kc][2] = *reinterpret_cast<const uint32_t*>(&sm[row * KST_ + kc * 16 + 8 + 2 * tg]);
            q_a[u][kc][3] = *reinterpret_cast<const uint32_t*>(&sm[(row + 8) * KST_ + kc * 16 + 8 + 2 * tg]);
        }
    }
    __syncthreads();   // Q staging region free for kv buffers

    // ---- Prefetch kv tile 0 into buf 0 ----
    {
        #pragma unroll
        for (int i = 0; i < 2; i++) {          // K: 256 chunks
            int idx = tid + i * 128;
            int r = idx >> 3, c = (idx & 7) * 8;
            cpb16(&sm[r * KST_ + c], kbase + (size_t)r * D_ + c);
        }
        #pragma unroll
        for (int i = 0; i < 2; i++) {          // Vt: 256 chunks
            int idx = tid + i * 128;
            int d = idx >> 2, c = (idx & 3) * 8;
            cpb16(&sm[32 * KST_ + d * VST_ + c], vtbase + (size_t)d * N_ + c);
        }
        cp_commit();
    }

    float o[2][8][4] = {};
    float mr[2][2] = {{neg_inf(), neg_inf()}, {neg_inf(), neg_inf()}};
    float lr[2][2] = {};
    int qrow[2];
    qrow[0] = q0 + warp * 32 + g;
    qrow[1] = qrow[0] + 16;

    for (int t = 0; t < NKT_; t++) {
        cp_wait<0>();
        __syncthreads();

        if (t + 1 < NKT_) {
            const __half* kb2 = kbase + (size_t)(t + 1) * KT_ * D_;
            const __half* vb2 = vtbase + (size_t)(t + 1) * KT_;
            __half* dst = sm + ((t + 1) & 1) * BUFH_;
            #pragma unroll
            for (int i = 0; i < 2; i++) {
                int idx = tid + i * 128;
                int r = idx >> 3, c = (idx & 7) * 8;
                cpb16(&dst[r * KST_ + c], kb2 + (size_t)r * D_ + c);
            }
            #pragma unroll
            for (int i = 0; i < 2; i++) {
                int idx = tid + i * 128;
                int d = idx >> 2, c = (idx & 3) * 8;
                cpb16(&dst[32 * KST_ + d * VST_ + c], vb2 + (size_t)d * N_ + c);
            }
            cp_commit();
        }

        const __half* Kc = sm + (t & 1) * BUFH_;
        const __half* Vc = Kc + 32 * KST_;
        const int kv0 = t * KT_;
        const int clean = __ldg(fb0 + (t >> 1)) & __ldg(fb1 + (t >> 1));

        // S = Q @ K^T (log2 units): 4 k16 chunks x 4 n-tiles, fragments shared by u
        float s[2][4][4] = {};
        #pragma unroll
        for (int kc = 0; kc < 4; kc++) {
            #pragma unroll
            for (int nt = 0; nt < 4; nt++) {
                uint32_t bfr[2];
                const int kb = (nt * 8 + g) * KST_ + kc * 16 + 2 * tg;
                bfr[0] = *reinterpret_cast<const uint32_t*>(&Kc[kb]);
                bfr[1] = *reinterpret_cast<const uint32_t*>(&Kc[kb + 8]);
                mma16h(s[0][nt], q_a[0][kc], bfr);
                mma16h(s[1][nt], q_a[1][kc], bfr);
            }
        }

        if (!clean) {
            #pragma unroll
            for (int u = 0; u < 2; u++) {
                #pragma unroll
                for (int nt = 0; nt < 4; nt++) {
                    const int col = kv0 + nt * 8 + 2 * tg;
                    int2 mA = *reinterpret_cast<const int2*>(mbase + (size_t)qrow[u] * N_ + col);
                    int2 mB = *reinterpret_cast<const int2*>(mbase + (size_t)(qrow[u] + 8) * N_ + col);
                    if (!mA.x) s[u][nt][0] = neg_inf();
                    if (!mA.y) s[u][nt][1] = neg_inf();
                    if (!mB.x) s[u][nt][2] = neg_inf();
                    if (!mB.y) s[u][nt][3] = neg_inf();
                }
            }
        }

        // Online softmax (log2 domain), per group u, rows g and g+8
        #pragma unroll
        for (int u = 0; u < 2; u++) {
            float mx0 = neg_inf(), mx1 = neg_inf();
            #pragma unroll
            for (int nt = 0; nt < 4; nt++) {
                mx0 = fmaxf(mx0, fmaxf(s[u][nt][0], s[u][nt][1]));
                mx1 = fmaxf(mx1, fmaxf(s[u][nt][2], s[u][nt][3]));
            }
            mx0 = fmaxf(mx0, __shfl_xor_sync(0xffffffffu, mx0, 1));
            mx0 = fmaxf(mx0, __shfl_xor_sync(0xffffffffu, mx0, 2));
            mx1 = fmaxf(mx1, __shfl_xor_sync(0xffffffffu, mx1, 1));
            mx1 = fmaxf(mx1, __shfl_xor_sync(0xffffffffu, mx1, 2));
            const float mn0 = fmaxf(mr[u][0], mx0), mn1 = fmaxf(mr[u][1], mx1);
            const float sc0 = fexp2(fmaxf(mr[u][0] - mn0, -120.0f));
            const float sc1 = fexp2(fmaxf(mr[u][1] - mn1, -120.0f));
            float sum0 = 0.0f, sum1 = 0.0f;
            #pragma unroll
            for (int nt = 0; nt < 4; nt++) {
                float p0 = fexp2(fmaxf(s[u][nt][0] - mn0, -120.0f));
                float p1 = fexp2(fmaxf(s[u][nt][1] - mn0, -120.0f));
                float p2 = fexp2(fmaxf(s[u][nt][2] - mn1, -120.0f));
                float p3 = fexp2(fmaxf(s[u][nt][3] - mn1, -120.0f));
                s[u][nt][0] = p0; s[u][nt][1] = p1; s[u][nt][2] = p2; s[u][nt][3] = p3;
                sum0 += p0 + p1; sum1 += p2 + p3;
            }
            sum0 += __shfl_xor_sync(0xffffffffu, sum0, 1);
            sum0 += __shfl_xor_sync(0xffffffffu, sum0, 2);
            sum1 += __shfl_xor_sync(0xffffffffu, sum1, 1);
            sum1 += __shfl_xor_sync(0xffffffffu, sum1, 2);
            lr[u][0] = lr[u][0] * sc0 + sum0; lr[u][1] = lr[u][1] * sc1 + sum1;
            mr[u][0] = mn0; mr[u][1] = mn1;

            #pragma unroll
            for (int dt = 0; dt < 8; dt++) {
                o[u][dt][0] *= sc0; o[u][dt][1] *= sc0;
                o[u][dt][2] *= sc1; o[u][dt][3] *= sc1;
            }
        }

        // O += P @ V : fp16 k16. P a-frags via quad shfls + f16x2 packs;
        // V fragments from transposed smem, each loaded once (feed both u).
        #pragma unroll
        for (int kc2 = 0; kc2 < 2; kc2++) {
            const int srcC = (g << 2) | tg;
            uint32_t a[2][4];
            #pragma unroll
            for (int u = 0; u < 2; u++) {
                float v0 = __shfl_sync(0xffffffffu, s[u][kc2 * 2][0], srcC);
                float v1 = __shfl_sync(0xffffffffu, s[u][kc2 * 2][1], srcC);
                float v2 = __shfl_sync(0xffffffffu, s[u][kc2 * 2][2], srcC);
                float v3 = __shfl_sync(0xffffffffu, s[u][kc2 * 2][3], srcC);
                float w0 = __shfl_sync(0xffffffffu, s[u][kc2 * 2 + 1][0], srcC);
                float w1 = __shfl_sync(0xffffffffu, s[u][kc2 * 2 + 1][1], srcC);
                float w2 = __shfl_sync(0xffffffffu, s[u][kc2 * 2 + 1][2], srcC);
                float w3 = __shfl_sync(0xffffffffu, s[u][kc2 * 2 + 1][3], srcC);
                a[u][0] = packh(v1, v0);   // row g,   k = 2tg, 2tg+1
                a[u][1] = packh(v3, v2);   // row g+8, k = 2tg, 2tg+1
                a[u][2] = packh(w1, w0);   // row g,   k = 8+2tg, 8+2tg+1
                a[u][3] = packh(w3, w2);   // row g+8, k = 8+2tg
            }
            #pragma unroll
            for (int dt = 0; dt < 8; dt++) {
                uint32_t bfr[2];
                const int vb = (dt * 8 + g) * VST_ + kc2 * 16 + 2 * tg;
                bfr[0] = *reinterpret_cast<const uint32_t*>(&Vc[vb]);
                bfr[1] = *reinterpret_cast<const uint32_t*>(&Vc[vb + 8]);
                mma16h(o[0][dt], a[0], bfr);
                mma16h(o[1][dt], a[1], bfr);
            }
        }
    }

    // Epilogue: normalize and recombine heads
    #pragma unroll
    for (int u = 0; u < 2; u++) {
        const float il0 = 1.0f / lr[u][0], il1 = 1.0f / lr[u][1];
        #pragma unroll
        for (int dt = 0; dt < 8; dt++) {
            const int dd = h * 64 + dt * 8 + 2 * tg;
            *reinterpret_cast<float2*>(&g_att[(size_t)(b * N_ + qrow[u]) * E_ + dd]) =
                make_float2(o[u][dt][0] * il0, o[u][dt][1] * il0);
            *reinterpret_cast<float2*>(&g_att[(size_t)(b * N_ + qrow[u] + 8) * E_ + dd]) =
                make_float2(o[u][dt][2] * il1, o[u][dt][3] * il1);
        }
    }
}

// ---------------------------------------------------------------------------
extern "C" void kernel_launch(void* const* d_in, const int* in_sizes, int n_in,
                              void* d_out, int out_size)
{
    const float* Q    = (const float*)d_in[0];
    const float* K    = (const float*)d_in[1];
    const float* V    = (const float*)d_in[2];
    const int*   mask = (const int*)  d_in[3];
    const float* Wq   = (const float*)d_in[4];
    const float* Wk   = (const float*)d_in[5];
    const float* Wv   = (const float*)d_in[6];
    const float* Wo   = (const float*)d_in[7];
    const float* bo   = (const float*)d_in[8];
    const float* tau  = (const float*)d_in[9];
    float* out = (float*)d_out;

    const int gemm_smem = 2 * GBUFB_;   // 65536

    cudaFuncSetAttribute(gemm_qkv, cudaFuncAttributeMaxDynamicSharedMemorySize, gemm_smem);
    cudaFuncSetAttribute(gemm_out, cudaFuncAttributeMaxDynamicSharedMemorySize, gemm_smem);

    split_w<<<dim3((int)(WBE_ / 1024), 4), 256>>>(Wq, Wk, Wv, Wo);
    mask_flags<<<dim3(NT_, NT_, B_), 256>>>(mask);

    gemm_qkv<<<dim3(E_ / 64, M_ / 128, 3), 256, gemm_smem>>>(Q, K, V, tau);

    // grid.x = heads (fastest) so the 8 heads sharing a mask tile are adjacent -> L2 reuse
    attn_tc<<<dim3(H_, N_ / 128, B_), 128>>>(mask);

    gemm_out<<<dim3(E_ / 64, M_ / 128), 256, gemm_smem>>>(bo, out);
}